// round 14
// baseline (speedup 1.0000x reference)
#include <cuda_runtime.h>
#include <cuda_bf16.h>
#include <math.h>
#include <stdint.h>

#define D1 48
#define H1 40
#define W1 48
#define V1 (D1*H1*W1)
#define D2 96
#define H2 80
#define W2 96
#define V2 (D2*H2*W2)

// fp32 scratch arena
constexpr size_t N_XIN1  = 368ull * V1;
constexpr size_t N_XIN2  = 110ull * V2;
constexpr size_t N_CTX   = 16ull  * V1;
constexpr size_t N_VEL   = 3ull   * V1;
constexpr size_t N_VELUP = 3ull   * V2;
constexpr size_t N_XOUT2 = 16ull  * V2;
constexpr size_t N_VELUP2= 3ull   * V2;
constexpr size_t O_XIN1=0, O_XIN2=O_XIN1+N_XIN1, O_CTX=O_XIN2+N_XIN2, O_VEL=O_CTX+N_CTX,
  O_VELUP=O_VEL+N_VEL, O_XOUT2=O_VELUP+N_VELUP, O_VELUP2=O_XOUT2+N_XOUT2;
constexpr size_t ARENA_TOTAL = O_VELUP2 + N_VELUP2;

__device__ float  g_arena[ARENA_TOTAL];
__device__ double g_red[4];
__device__ float  g_ms[2];

// interleaved bf16 hi/lo activation arenas: [voxel][Ctot]
__device__ __align__(16) __nv_bfloat16 g_xh1[(size_t)V1*368];
__device__ __align__(16) __nv_bfloat16 g_xl1[(size_t)V1*368];
__device__ __align__(16) __nv_bfloat16 g_xh2[(size_t)V2*112];
__device__ __align__(16) __nv_bfloat16 g_xl2[(size_t)V2*112];

// weights [tap][coutNT][cinPad] bf16 hi/lo
constexpr size_t WOFF0=0;
constexpr size_t WOFF1=WOFF0+27ull*64*256;
constexpr size_t WOFF2=WOFF1+27ull*48*320;
constexpr size_t WOFF3=WOFF2+27ull*32*384;
constexpr size_t WOFF4=WOFF3+27ull*16*384;
constexpr size_t WOFF5=WOFF4+27ull*32*128;
constexpr size_t WTOT =WOFF5+27ull*16*128;
__device__ __align__(16) __nv_bfloat16 g_wh[WTOT];
__device__ __align__(16) __nv_bfloat16 g_wl[WTOT];

#define SWZ(o) ((o) ^ (((o)>>3)&0x70))

// ---------- helpers ----------
__device__ __forceinline__ uint32_t smem_u32(const void* p){
    uint32_t a; asm("{ .reg .u64 t; cvta.to.shared.u64 t, %1; cvt.u32.u64 %0, t; }":"=r"(a):"l"(p)); return a;
}
__device__ __forceinline__ void ldsm4(uint32_t* r, uint32_t addr){
    asm volatile("ldmatrix.sync.aligned.m8n8.x4.shared.b16 {%0,%1,%2,%3},[%4];"
        : "=r"(r[0]),"=r"(r[1]),"=r"(r[2]),"=r"(r[3]) : "r"(addr));
}
__device__ __forceinline__ void mma16816(float* c, const uint32_t* a, const uint32_t* b){
    asm volatile("mma.sync.aligned.m16n8k16.row.col.f32.bf16.bf16.f32 "
        "{%0,%1,%2,%3},{%4,%5,%6,%7},{%8,%9},{%0,%1,%2,%3};"
        : "+f"(c[0]),"+f"(c[1]),"+f"(c[2]),"+f"(c[3])
        : "r"(a[0]),"r"(a[1]),"r"(a[2]),"r"(a[3]),"r"(b[0]),"r"(b[1]));
}
__device__ __forceinline__ void split_hl(float v,__nv_bfloat16& h,__nv_bfloat16& l){
    h=__float2bfloat16(v);
    l=__float2bfloat16(v-__bfloat162float(h));
}

// ---------- small kernels ----------
__global__ void k_zero_red(){ if(threadIdx.x<4) g_red[threadIdx.x]=0.0; }
__global__ void k_reduce4(const float4* __restrict__ x,int n4,int slot){
    __shared__ double ss[256],sq[256];
    double s=0,q=0;
    for(int i=blockIdx.x*blockDim.x+threadIdx.x;i<n4;i+=gridDim.x*blockDim.x){
        float4 v=x[i];
        double a=v.x,b=v.y,c=v.z,d=v.w;
        s+=a+b+c+d; q+=a*a+b*b+c*c+d*d;
    }
    int t=threadIdx.x; ss[t]=s; sq[t]=q; __syncthreads();
    for(int o=128;o>0;o>>=1){ if(t<o){ss[t]+=ss[t+o];sq[t]+=sq[t+o];} __syncthreads(); }
    if(t==0){ atomicAdd(&g_red[slot],ss[0]); atomicAdd(&g_red[slot+1],sq[0]); }
}
__global__ void k_finalize_ms(double n){
    double ma=g_red[0]/n, mb=g_red[2]/n;
    double va=(g_red[1]-g_red[0]*g_red[0]/n)/(n-1.0), vb=(g_red[3]-g_red[2]*g_red[2]/n)/(n-1.0);
    double s=0.5*(sqrt(va)+sqrt(vb));
    g_ms[0]=(float)(0.5*(ma+mb)); g_ms[1]=(float)(1.0/s);
}
// fp32 channel-major -> hi/lo interleaved [vox][Ctot] at channel offset c0.
// Tiled transpose: coalesced reads along vox (64-voxel tile), smem transpose,
// contiguous interleaved writes. Vn must be divisible by 64 (V1, V2 both are).
__global__ void k_pack_hl_t(const float* __restrict__ src,__nv_bfloat16* __restrict__ dh,
                            __nv_bfloat16* __restrict__ dl,size_t Vn,int Ctot,int c0,int nc){
    __shared__ float s[64*128];
    const size_t v0=(size_t)blockIdx.x*64;
    const int tid=threadIdx.x;
    for(int idx=tid;idx<nc*64;idx+=256){
        int c=idx>>6, j=idx&63;
        s[c*64+j]=src[(size_t)c*Vn+v0+j];
    }
    __syncthreads();
    const int tot=64*nc;
    for(int idx=tid;idx<tot;idx+=256){
        int vox=idx/nc, c=idx-vox*nc;
        float v=s[c*64+vox];
        __nv_bfloat16 h,l; split_hl(v,h,l);
        size_t o=(v0+vox)*(size_t)Ctot+c0+c;
        dh[o]=h; dl[o]=l;
    }
}
__global__ void k_prep_w(const float* __restrict__ src,__nv_bfloat16* __restrict__ dh,
                         __nv_bfloat16* __restrict__ dl,int Cout,int NT,int Cin,int Cpad){
    int n=NT*Cpad*27;
    for(int e=blockIdx.x*blockDim.x+threadIdx.x;e<n;e+=gridDim.x*blockDim.x){
        int ci=e%Cpad, co=(e/Cpad)%NT, tap=e/(Cpad*NT);
        float v=(ci<Cin&&co<Cout)?src[((size_t)co*Cin+ci)*27+tap]:0.f;
        __nv_bfloat16 h,l; split_hl(v,h,l);
        size_t d=((size_t)tap*NT+co)*Cpad+ci; dh[d]=h; dl[d]=l;
    }
}

// ---------- warp / final ----------
__device__ __forceinline__ void corners(float cz,float cy,float cx,int D,int H,int W,int HW,
                                        int* idx,float* w8){
    float fz0=floorf(cz),fy0=floorf(cy),fx0=floorf(cx);
    int z0=(int)fz0,y0=(int)fy0,x0=(int)fx0;
    float fz=cz-fz0,fy=cy-fy0,fx=cx-fx0;
    float wz[2]={1.f-fz,fz},wy[2]={1.f-fy,fy},wx[2]={1.f-fx,fx};
    #pragma unroll
    for(int dz=0;dz<2;dz++)
    #pragma unroll
    for(int dy=0;dy<2;dy++)
    #pragma unroll
    for(int dx=0;dx<2;dx++){
        int zi=z0+dz,yi=y0+dy,xi=x0+dx;
        bool v=(zi>=0&&zi<D&&yi>=0&&yi<H&&xi>=0&&xi<W);
        int zc=min(max(zi,0),D-1),yc=min(max(yi,0),H-1),xc=min(max(xi,0),W-1);
        int k=dz*4+dy*2+dx;
        idx[k]=zc*HW+yc*W+xc; w8[k]=v?wz[dz]*wy[dy]*wx[dx]:0.f;
    }
}
__global__ void k_warp(const float* __restrict__ vol,const float* __restrict__ flow,
                       float* __restrict__ out,int C,int D,int H,int W,int addFlow){
    size_t V=(size_t)D*H*W; int HW=H*W;
    for(size_t p=blockIdx.x*(size_t)blockDim.x+threadIdx.x;p<V;p+=(size_t)gridDim.x*blockDim.x){
        int z=(int)(p/HW),r=(int)(p%HW),y=r/W,x=r%W;
        int idx[8]; float w8[8];
        corners(z+flow[p],y+flow[V+p],x+flow[2*V+p],D,H,W,HW,idx,w8);
        for(int c=0;c<C;c++){
            const float* vc=vol+(size_t)c*V; float a=0.f;
            #pragma unroll
            for(int k=0;k<8;k++) a+=w8[k]*vc[idx[k]];
            out[(size_t)c*V+p]=a+(addFlow?flow[(size_t)c*V+p]:0.f);
        }
    }
}
// final: 4 voxels/thread; vf = (warp(disp2, vel2) + vel2 - disp_up) / (1 - t)
__global__ void k_final(const float* __restrict__ disp2,const float* __restrict__ vel2,
                        const float* __restrict__ dispup,const float* __restrict__ tptr,
                        float* __restrict__ out){
    const int D=D2,H=H2,W=W2,HW=H*W; const size_t V=(size_t)V2;
    float inv=1.f/(1.f-tptr[0]);
    const int Wq=W>>2, nquad=D*H*Wq;
    for(int q=blockIdx.x*blockDim.x+threadIdx.x;q<nquad;q+=gridDim.x*blockDim.x){
        int xb=(q%Wq)<<2; int r=q/Wq; int y=r%H; int z=r/H;
        size_t p=(size_t)z*HW+(size_t)y*W+xb;
        float4 fz4=*(const float4*)(vel2+p);
        float4 fy4=*(const float4*)(vel2+V+p);
        float4 fx4=*(const float4*)(vel2+2*V+p);
        float fzv[4]={fz4.x,fz4.y,fz4.z,fz4.w};
        float fyv[4]={fy4.x,fy4.y,fy4.z,fy4.w};
        float fxv[4]={fx4.x,fx4.y,fx4.z,fx4.w};
        float res[3][4];
        #pragma unroll
        for(int vx=0;vx<4;vx++){
            int idx[8]; float w8[8];
            corners(z+fzv[vx],y+fyv[vx],xb+vx+fxv[vx],D,H,W,HW,idx,w8);
            #pragma unroll
            for(int c=0;c<3;c++){
                const float* vc=disp2+(size_t)c*V; float a=0.f;
                #pragma unroll
                for(int k=0;k<8;k++) a+=w8[k]*vc[idx[k]];
                float flowc=(c==0)?fzv[vx]:((c==1)?fyv[vx]:fxv[vx]);
                res[c][vx]=(a+flowc-dispup[(size_t)c*V+p+vx])*inv;
            }
        }
        #pragma unroll
        for(int c=0;c<3;c++)
            *(float4*)(out+(size_t)c*V+p)=make_float4(res[c][0],res[c][1],res[c][2],res[c][3]);
    }
}

// ---------- resizes ----------
__device__ __forceinline__ int taps_down(int o,int n,int* ti,float* tw){
    const float raw[4]={1.f,3.f,3.f,1.f}; int m=0; float tot=0.f;
    #pragma unroll
    for(int k=0;k<4;k++){int t=2*o-1+k; if(t>=0&&t<n){ti[m]=t;tw[m]=raw[k];tot+=raw[k];m++;}}
    float inv=1.f/tot; for(int i=0;i<m;i++)tw[i]*=inv; return m;
}
__global__ void k_resize_down(const float* __restrict__ in,float* __restrict__ out,float scale){
    int n=3*V1;
    for(int idx=blockIdx.x*blockDim.x+threadIdx.x;idx<n;idx+=gridDim.x*blockDim.x){
        int c=idx/V1,p=idx%V1,z=p/(H1*W1),r=p%(H1*W1),y=r/W1,x=r%W1;
        int zi[4],yi[4],xi[4]; float zw[4],yw[4],xw[4];
        int mz=taps_down(z,D2,zi,zw),my=taps_down(y,H2,yi,yw),mx=taps_down(x,W2,xi,xw);
        const float* ic=in+(size_t)c*V2; float a=0.f;
        for(int iz=0;iz<mz;iz++)for(int iy=0;iy<my;iy++){
            float wzy=zw[iz]*yw[iy];
            const float* row=ic+(size_t)zi[iz]*(H2*W2)+yi[iy]*W2;
            for(int ix=0;ix<mx;ix++)a+=wzy*xw[ix]*row[xi[ix]];
        }
        out[idx]=a*scale;
    }
}
__device__ __forceinline__ void taps_up(int o,int n,int& i0,int& i1,float& w0,float& w1){
    int j=o>>1;
    if((o&1)==0){ if(j==0){i0=0;i1=0;w0=1.f;w1=0.f;} else {i0=j-1;i1=j;w0=0.25f;w1=0.75f;} }
    else { if(j+1>=n){i0=j;i1=j;w0=1.f;w1=0.f;} else {i0=j;i1=j+1;w0=0.75f;w1=0.25f;} }
}
__global__ void k_resize_up(const float* __restrict__ in,float* __restrict__ out,int C,float scale){
    size_t n=(size_t)C*V2;
    for(size_t idx=blockIdx.x*(size_t)blockDim.x+threadIdx.x;idx<n;idx+=(size_t)gridDim.x*blockDim.x){
        int c=(int)(idx/V2),p=(int)(idx%V2),z=p/(H2*W2),r=p%(H2*W2),y=r/W2,x=r%W2;
        int z0,z1,y0,y1,x0,x1; float wz0,wz1,wy0,wy1,wx0,wx1;
        taps_up(z,D1,z0,z1,wz0,wz1); taps_up(y,H1,y0,y1,wy0,wy1); taps_up(x,W1,x0,x1,wx0,wx1);
        const float* ic=in+(size_t)c*V1; const int HW=H1*W1;
        float a=wz0*(wy0*(wx0*ic[z0*HW+y0*W1+x0]+wx1*ic[z0*HW+y0*W1+x1])+
                     wy1*(wx0*ic[z0*HW+y1*W1+x0]+wx1*ic[z0*HW+y1*W1+x1]))+
                wz1*(wy0*(wx0*ic[z1*HW+y0*W1+x0]+wx1*ic[z1*HW+y0*W1+x1])+
                     wy1*(wx0*ic[z1*HW+y1*W1+x0]+wx1*ic[z1*HW+y1*W1+x1]));
        out[idx]=a*scale;
    }
}

// ---------- cost volume, 4 voxels/thread, fused pair-normalization ----------
template <int MD>
__global__ void __launch_bounds__(128)
k_costvol4(const float* __restrict__ f1,const float* __restrict__ f2,
           float* __restrict__ out,int C,int D,int H,int W){
    const int N=2*MD+1;
    const int NW=2*MD+4;
    size_t V=(size_t)D*H*W; const int HW=H*W;
    const int i=blockIdx.y;
    const float invC=1.f/(float)C;
    const float m=g_ms[0], is=g_ms[1];
    const int Wq=W>>2;
    const int nquad=D*H*Wq;
    for(int q=blockIdx.x*blockDim.x+threadIdx.x;q<nquad;q+=gridDim.x*blockDim.x){
        int xb=(q%Wq)<<2; int r=q/Wq; int y=r%H; int z=r/H;
        size_t p=(size_t)z*HW+(size_t)y*W+xb;
        float acc[N*N][4];
        #pragma unroll
        for(int t=0;t<N*N;t++)
        #pragma unroll
        for(int vx=0;vx<4;vx++) acc[t][vx]=0.f;
        int zq=z+i-MD;
        if(zq>=0&&zq<D){
            for(int c=0;c<C;c++){
                float4 f1v=*(const float4*)(f1+(size_t)c*V+p);
                float tv[4]={(f1v.x-m)*is,(f1v.y-m)*is,(f1v.z-m)*is,(f1v.w-m)*is};
                const float* base=f2+(size_t)c*V+(size_t)zq*HW;
                #pragma unroll
                for(int j=0;j<N;j++){
                    int yq=y+j-MD; if(yq<0||yq>=H)continue;
                    const float* row=base+yq*W;
                    float v[NW];
                    float4 mm=*(const float4*)(row+xb);
                    v[MD+0]=(mm.x-m)*is; v[MD+1]=(mm.y-m)*is;
                    v[MD+2]=(mm.z-m)*is; v[MD+3]=(mm.w-m)*is;
                    if(MD==2){
                        if(xb>0){
                            float2 a2=*(const float2*)(row+xb-2);
                            v[0]=(a2.x-m)*is; v[1]=(a2.y-m)*is;
                        } else { v[0]=0.f; v[1]=0.f; }
                        if(xb+4<W){
                            float2 d2=*(const float2*)(row+xb+4);
                            v[6]=(d2.x-m)*is; v[7]=(d2.y-m)*is;
                        } else { v[6]=0.f; v[7]=0.f; }
                    } else {
                        v[0]=(xb>0)?(row[xb-1]-m)*is:0.f;
                        v[5]=(xb+4<W)?(row[xb+4]-m)*is:0.f;
                    }
                    #pragma unroll
                    for(int k=0;k<N;k++)
                    #pragma unroll
                    for(int vx=0;vx<4;vx++)
                        acc[j*N+k][vx]+=tv[vx]*v[vx+k];
                }
            }
        }
        #pragma unroll
        for(int j=0;j<N;j++)
        #pragma unroll
        for(int k=0;k<N;k++){
            float4 o;
            float* ap=acc[j*N+k];
            float a0=ap[0]*invC, a1=ap[1]*invC, a2=ap[2]*invC, a3=ap[3]*invC;
            o.x=(a0>=0.f)?a0:0.05f*a0;
            o.y=(a1>=0.f)?a1:0.05f*a1;
            o.z=(a2>=0.f)?a2:0.05f*a2;
            o.w=(a3>=0.f)?a3:0.05f*a3;
            *(float4*)(out+(size_t)((i*N+j)*N+k)*V+p)=o;
        }
    }
}

// ---------- unrolled per-tap MMA compute ----------
template<int KSN,int MF,int NB>
__device__ __forceinline__ void tap_compute(
    uint32_t sA_h,uint32_t sA_l,uint32_t sB_h,uint32_t sB_l,
    const uint32_t (&arow)[MF],int nbase,int bq,int bi,
    float (&acc)[MF][2*NB][4]){
    #pragma unroll
    for(int ks=0;ks<KSN;ks++){
        uint32_t ah[MF][4], al[MF][4];
        #pragma unroll
        for(int mf=0;mf<MF;mf++){
            uint32_t o=SWZ(arow[mf]+(uint32_t)ks*32);
            ldsm4(ah[mf],sA_h+o);
            ldsm4(al[mf],sA_l+o);
        }
        uint32_t bh[NB][4], bl[NB][4];
        #pragma unroll
        for(int g=0;g<NB;g++){
            int row=nbase+g*16+((bq>>1)<<3)+bi;
            uint32_t bo=SWZ((uint32_t)row*128+(uint32_t)(bq&1)*16+(uint32_t)ks*32);
            ldsm4(bh[g],sB_h+bo);
            ldsm4(bl[g],sB_l+bo);
        }
        #pragma unroll
        for(int mf=0;mf<MF;mf++)
        #pragma unroll
        for(int g=0;g<NB;g++)
        #pragma unroll
        for(int h=0;h<2;h++){
            float* C=acc[mf][g*2+h];
            mma16816(C,ah[mf],&bh[g][2*h]);
            mma16816(C,ah[mf],&bl[g][2*h]);
            mma16816(C,al[mf],&bh[g][2*h]);
        }
    }
}

// ---------- mma.sync implicit-GEMM conv (3x3x3 SAME), hi/lo bf16 ----------
template<int NT>
__global__ void __launch_bounds__(256,2)
k_wmma_conv(const __nv_bfloat16* __restrict__ xh,const __nv_bfloat16* __restrict__ xl,
            const __nv_bfloat16* __restrict__ wh,const __nv_bfloat16* __restrict__ wl,
            const float* __restrict__ bias,
            __nv_bfloat16* oh,__nv_bfloat16* ol,float* of32,
            int Ctot,int Cin,int Cpad,int Dd,int Hh,int Ww,int coutOff){
    constexpr int MF=(NT==64)?2:1;
    constexpr int NF=(NT==64)?4:(NT/8);
    constexpr int NB=NF/2;
    constexpr uint32_t NTB=(uint32_t)NT*128;
    extern __shared__ __align__(128) char sm[];
    const uint32_t sA_h=smem_u32(sm);
    const uint32_t sA_l=sA_h+46080;
    const uint32_t sB_h=sA_h+92160;
    const uint32_t sB_l=sB_h+NTB;

    const int tid=threadIdx.x, lane=tid&31, wid=tid>>5;
    const int x0=blockIdx.x*8, y0=blockIdx.y*4, z0=blockIdx.z*4;
    const int HW=Hh*Ww; const size_t V=(size_t)Dd*HW;
    const int mbase=(NT==64)?(wid&3)*32:wid*16;
    const int nbase=(NT==64)?(wid>>2)*32:0;

    float acc[MF][NF][4];
    #pragma unroll
    for(int a=0;a<MF;a++)
    #pragma unroll
    for(int b=0;b<NF;b++)
    #pragma unroll
    for(int c=0;c<4;c++) acc[a][b][c]=0.f;

    int lmx[MF],lmy[MF],lmz[MF];
    #pragma unroll
    for(int mf=0;mf<MF;mf++){
        int m=mbase+mf*16+(lane&15);
        lmx[mf]=m&7; lmy[mf]=(m>>3)&3; lmz[mf]=m>>5;
    }
    const uint32_t khoff=(uint32_t)(lane>>4)*16;
    const int bq=lane>>3, bi=lane&7;

    const int nchunk=(Cin+63)>>6;
    for(int ch=0;ch<nchunk;ch++){
        const int ci0=ch<<6;
        const int kreal=min(64,Cin-ci0);
        const int ksn=(kreal+15)>>4;
        const int nseg=2*ksn;
        __syncthreads();
        // ---- stage A halo ----
        for(int r=tid;r<360;r+=256){
            int hx=r%10, hy=(r/10)%6, hz=r/60;
            int gx=x0+hx-1, gy=y0+hy-1, gz=z0+hz-1;
            bool val=(gx>=0&&gx<Ww&&gy>=0&&gy<Hh&&gz>=0&&gz<Dd);
            size_t vox=val?((size_t)gz*HW+(size_t)gy*Ww+gx):0;
            const __nv_bfloat16* ph=xh+vox*(size_t)Ctot+ci0;
            const __nv_bfloat16* pl=xl+vox*(size_t)Ctot+ci0;
            uint32_t rb=(uint32_t)r*128;
            for(int s=0;s<nseg;s++){
                uint4 vh=make_uint4(0,0,0,0), vl=make_uint4(0,0,0,0);
                if(val){
                    if(s*8+8<=kreal){ vh=*(const uint4*)(ph+s*8); vl=*(const uint4*)(pl+s*8); }
                    else if(s*8<kreal){
                        uint16_t th[8]={0,0,0,0,0,0,0,0}, tl[8]={0,0,0,0,0,0,0,0};
                        for(int j=0;j<8;j++) if(s*8+j<kreal){
                            th[j]=((const uint16_t*)ph)[s*8+j];
                            tl[j]=((const uint16_t*)pl)[s*8+j];
                        }
                        vh=*(uint4*)th; vl=*(uint4*)tl;
                    }
                }
                uint32_t off=SWZ(rb+(uint32_t)s*16);
                *(uint4*)(sm+off)=vh;
                *(uint4*)(sm+46080+off)=vl;
            }
        }
        // ---- taps ----
        for(int tap=0;tap<27;tap++){
            __syncthreads();
            for(int s=tid;s<NT*nseg;s+=256){
                int n=s/nseg, seg=s-n*nseg;
                size_t wb=((size_t)tap*NT+n)*Cpad+ci0+seg*8;
                uint32_t off=SWZ((uint32_t)n*128+(uint32_t)seg*16);
                *(uint4*)(sm+92160+off)=*(const uint4*)(wh+wb);
                *(uint4*)(sm+92160+NTB+off)=*(const uint4*)(wl+wb);
            }
            __syncthreads();
            const int dz=tap/9-1, dy=(tap/3)%3-1, dx=tap%3-1;
            uint32_t arow[MF];
            #pragma unroll
            for(int mf=0;mf<MF;mf++){
                int hr=((lmz[mf]+dz+1)*6+(lmy[mf]+dy+1))*10+(lmx[mf]+dx+1);
                arow[mf]=(uint32_t)hr*128+khoff;
            }
            switch(ksn){
                case 4: tap_compute<4,MF,NB>(sA_h,sA_l,sB_h,sB_l,arow,nbase,bq,bi,acc); break;
                case 3: tap_compute<3,MF,NB>(sA_h,sA_l,sB_h,sB_l,arow,nbase,bq,bi,acc); break;
                case 2: tap_compute<2,MF,NB>(sA_h,sA_l,sB_h,sB_l,arow,nbase,bq,bi,acc); break;
                default: tap_compute<1,MF,NB>(sA_h,sA_l,sB_h,sB_l,arow,nbase,bq,bi,acc); break;
            }
        }
    }

    // ---- epilogue ----
    #pragma unroll
    for(int mf=0;mf<MF;mf++)
    #pragma unroll
    for(int nf=0;nf<NF;nf++)
    #pragma unroll
    for(int rp=0;rp<2;rp++){
        int m=mbase+mf*16+(lane>>2)+rp*8;
        int n=nbase+nf*8+((lane&3)<<1);
        int gx=x0+(m&7), gy=y0+((m>>3)&3), gz=z0+(m>>5);
        size_t vox=(size_t)gz*HW+(size_t)gy*Ww+gx;
        float v0=acc[mf][nf][rp*2+0]+bias[n];
        float v1=acc[mf][nf][rp*2+1]+bias[n+1];
        v0=(v0>=0.f)?v0:0.02f*v0;
        v1=(v1>=0.f)?v1:0.02f*v1;
        if(oh!=nullptr){
            __nv_bfloat16 h0,l0,h1,l1;
            split_hl(v0,h0,l0); split_hl(v1,h1,l1);
            uint32_t ph_=(uint32_t)__bfloat16_as_ushort(h0)|((uint32_t)__bfloat16_as_ushort(h1)<<16);
            uint32_t pl_=(uint32_t)__bfloat16_as_ushort(l0)|((uint32_t)__bfloat16_as_ushort(l1)<<16);
            *(uint32_t*)(oh+vox*(size_t)Ctot+coutOff+n)=ph_;
            *(uint32_t*)(ol+vox*(size_t)Ctot+coutOff+n)=pl_;
        }
        if(of32!=nullptr){
            of32[(size_t)n*V+vox]=v0;
            of32[(size_t)(n+1)*V+vox]=v1;
        }
    }
}

// ---------- SIMT conv 16->3, 4 voxels/thread, row-reuse across dx taps ----------
__global__ void k_conv16_3(const float* __restrict__ in,const float* __restrict__ wg,
                           const float* __restrict__ bias,float* __restrict__ out,
                           int Dd,int Hh,int Ww){
    __shared__ float sw[1296]; __shared__ float sb[3];
    int tid=threadIdx.x;
    for(int l=tid;l<1296;l+=blockDim.x)sw[l]=wg[l];
    if(tid<3)sb[tid]=bias[tid];
    __syncthreads();
    const int HW=Hh*Ww; const size_t V=(size_t)Dd*HW;
    const int Wq=Ww>>2;
    const int nquad=Dd*Hh*Wq;
    for(int q=blockIdx.x*blockDim.x+tid;q<nquad;q+=gridDim.x*blockDim.x){
        int xq=q%Wq; int r=q/Wq; int y=r%Hh; int z=r/Hh;
        int xb=xq<<2;
        float a[3][4];
        #pragma unroll
        for(int o=0;o<3;o++)
        #pragma unroll
        for(int j=0;j<4;j++) a[o][j]=sb[o];
        for(int dz=-1;dz<=1;dz++){
            int zz=z+dz; if(zz<0||zz>=Dd)continue;
            for(int dy=-1;dy<=1;dy++){
                int yy=y+dy; if(yy<0||yy>=Hh)continue;
                int tap0=(dz+1)*9+(dy+1)*3;
                #pragma unroll 2
                for(int c=0;c<16;c++){
                    const float* row=in+(size_t)c*V+(size_t)zz*HW+(size_t)yy*Ww+xb;
                    float v[6];
                    float4 mid=*(const float4*)row;
                    v[1]=mid.x; v[2]=mid.y; v[3]=mid.z; v[4]=mid.w;
                    v[0]=(xb>0)?row[-1]:0.f;
                    v[5]=(xb+4<Ww)?row[4]:0.f;
                    #pragma unroll
                    for(int dx=0;dx<3;dx++){
                        float w0=sw[c*27+tap0+dx];
                        float w1=sw[(16+c)*27+tap0+dx];
                        float w2=sw[(32+c)*27+tap0+dx];
                        #pragma unroll
                        for(int j=0;j<4;j++){
                            float vv=v[j+dx];
                            a[0][j]+=vv*w0; a[1][j]+=vv*w1; a[2][j]+=vv*w2;
                        }
                    }
                }
            }
        }
        size_t p=(size_t)z*HW+(size_t)y*Ww+xb;
        #pragma unroll
        for(int o=0;o<3;o++)
            *(float4*)(out+(size_t)o*V+p)=make_float4(a[o][0],a[o][1],a[o][2],a[o][3]);
    }
}

// ---------- host ----------
template<int NT>
static void run_wconv(const __nv_bfloat16* xh,const __nv_bfloat16* xl,
                      const __nv_bfloat16* wh,const __nv_bfloat16* wl,const float* bias,
                      __nv_bfloat16* oh,__nv_bfloat16* ol,float* of32,
                      int Ctot,int Cin,int Cpad,int Dd,int Hh,int Ww,int coutOff){
    size_t smv=92160+2*(size_t)NT*128;
    cudaFuncSetAttribute(k_wmma_conv<NT>,cudaFuncAttributeMaxDynamicSharedMemorySize,(int)smv);
    dim3 g(Ww/8,Hh/4,Dd/4);
    k_wmma_conv<NT><<<g,256,smv>>>(xh,xl,wh,wl,bias,oh,ol,of32,Ctot,Cin,Cpad,Dd,Hh,Ww,coutOff);
}

extern "C" void kernel_launch(void* const* d_in,const int* in_sizes,int n_in,
                              void* d_out,int out_size){
    const float* t_ptr=(const float*)d_in[0];
    const float* dispup=(const float*)d_in[1];
    const float* fx=(const float*)d_in[2];
    const float* fy=(const float*)d_in[3];
    const float* fxu=(const float*)d_in[4];
    const float* fyu=(const float*)d_in[5];
    const float* ctx=(const float*)d_in[6];
    const float* w1_[5]={(const float*)d_in[7],(const float*)d_in[9],(const float*)d_in[11],
                         (const float*)d_in[13],(const float*)d_in[15]};
    const float* b1_[5]={(const float*)d_in[8],(const float*)d_in[10],(const float*)d_in[12],
                         (const float*)d_in[14],(const float*)d_in[16]};
    const float* w2_[3]={(const float*)d_in[17],(const float*)d_in[19],(const float*)d_in[21]};
    const float* b2_[3]={(const float*)d_in[18],(const float*)d_in[20],(const float*)d_in[22]};

    float* A; cudaGetSymbolAddress((void**)&A,g_arena);
    __nv_bfloat16 *xh1,*xl1,*xh2,*xl2,*wh,*wl;
    cudaGetSymbolAddress((void**)&xh1,g_xh1); cudaGetSymbolAddress((void**)&xl1,g_xl1);
    cudaGetSymbolAddress((void**)&xh2,g_xh2); cudaGetSymbolAddress((void**)&xl2,g_xl2);
    cudaGetSymbolAddress((void**)&wh,g_wh);   cudaGetSymbolAddress((void**)&wl,g_wl);

    float* xin1=A+O_XIN1;  float* xin2=A+O_XIN2;
    float* ctx16=A+O_CTX;  float* vel=A+O_VEL;   float* velup=A+O_VELUP;
    float* xout2=A+O_XOUT2;float* velup2=A+O_VELUP2;
    float* cv1=xin1;                  float* wx=xin1+157ull*V1;  float* disp=xin1+221ull*V1;
    float* cv2=xin2;                  float* wxu=xin2+43ull*V2;
    float* upctx=xin2+59ull*V2;       float* disp2=xin2+75ull*V2;
    float* outf=(float*)d_out;

    static cudaStream_t sB=nullptr;
    static cudaEvent_t evF=nullptr,evA=nullptr,evJ1=nullptr,
                       evB=nullptr,evJ2=nullptr,evC=nullptr,evJ3=nullptr;
    if(sB==nullptr){
        cudaStreamCreateWithFlags(&sB,cudaStreamNonBlocking);
        cudaEventCreateWithFlags(&evF,cudaEventDisableTiming);
        cudaEventCreateWithFlags(&evA,cudaEventDisableTiming);
        cudaEventCreateWithFlags(&evJ1,cudaEventDisableTiming);
        cudaEventCreateWithFlags(&evB,cudaEventDisableTiming);
        cudaEventCreateWithFlags(&evJ2,cudaEventDisableTiming);
        cudaEventCreateWithFlags(&evC,cudaEventDisableTiming);
        cudaEventCreateWithFlags(&evJ3,cudaEventDisableTiming);
    }

    const int TPB=256, GB1=(V1+TPB-1)/TPB, GB2=(V2+TPB-1)/TPB;
    cudaMemsetAsync(d_out,0,(size_t)out_size*sizeof(float),0);

    // ---- fork 0: weight prep + true-input packs ----
    cudaEventRecord(evF,0);
    cudaStreamWaitEvent(sB,evF,0);
    k_prep_w<<<512,256,0,sB>>>(w1_[0],wh+WOFF0,wl+WOFF0,64,64,224,256);
    k_prep_w<<<512,256,0,sB>>>(w1_[1],wh+WOFF1,wl+WOFF1,48,48,288,320);
    k_prep_w<<<512,256,0,sB>>>(w1_[2],wh+WOFF2,wl+WOFF2,32,32,336,384);
    k_prep_w<<<512,256,0,sB>>>(w1_[3],wh+WOFF3,wl+WOFF3,16,16,368,384);
    k_prep_w<<<256,256,0,sB>>>(w2_[0],wh+WOFF4,wl+WOFF4,32,32,78,128);
    k_prep_w<<<256,256,0,sB>>>(w2_[1],wh+WOFF5,wl+WOFF5,16,16,110,128);
    k_pack_hl_t<<<V1/64,256,0,sB>>>(fy,  xh1,xl1,V1,368,125,32);
    k_pack_hl_t<<<V1/64,256,0,sB>>>(ctx, xh1,xl1,V1,368,189,32);
    k_pack_hl_t<<<V2/64,256,0,sB>>>(fyu, xh2,xl2,V2,112,27,16);

    // ---- coarse chain ----
    k_resize_down<<<(3*V1+TPB-1)/TPB,TPB>>>(dispup,disp,0.5f);
    k_warp<<<GB1,TPB>>>(fx,disp,wx,32,D1,H1,W1,0);
    cudaEventRecord(evA,0);
    cudaStreamWaitEvent(sB,evA,0);
    k_pack_hl_t<<<V1/64,256,0,sB>>>(wx,  xh1,xl1,V1,368,157,32);
    k_pack_hl_t<<<V1/64,256,0,sB>>>(disp,xh1,xl1,V1,368,221,3);
    cudaEventRecord(evJ1,sB);

    k_zero_red<<<1,4>>>();
    k_reduce4<<<1024,256>>>((const float4*)wx,8*V1,0);
    k_reduce4<<<1024,256>>>((const float4*)fy,8*V1,2);
    k_finalize_ms<<<1,1>>>((double)(32*V1));
    {
        int nq=D1*H1*(W1/4);
        k_costvol4<2><<<dim3((nq+127)/128,5),128>>>(fy,wx,cv1,32,D1,H1,W1);
    }
    k_pack_hl_t<<<V1/64,256>>>(cv1, xh1,xl1,V1,368,0,  125);

    cudaStreamWaitEvent(0,evJ1,0);

    // fl1 dense block
    run_wconv<64>(xh1,xl1,wh+WOFF0,wl+WOFF0,b1_[0],xh1,xl1,nullptr,368,224,256,D1,H1,W1,224);
    run_wconv<48>(xh1,xl1,wh+WOFF1,wl+WOFF1,b1_[1],xh1,xl1,nullptr,368,288,320,D1,H1,W1,288);
    run_wconv<32>(xh1,xl1,wh+WOFF2,wl+WOFF2,b1_[2],xh1,xl1,nullptr,368,336,384,D1,H1,W1,336);
    run_wconv<16>(xh1,xl1,wh+WOFF3,wl+WOFF3,b1_[3],nullptr,nullptr,ctx16,368,368,384,D1,H1,W1,0);
    cudaEventRecord(evB,0);
    cudaStreamWaitEvent(sB,evB,0);
    k_resize_up<<<GB2*2,256,0,sB>>>(ctx16,upctx,16,1.0f);
    k_pack_hl_t<<<V2/64,256,0,sB>>>(upctx,xh2,xl2,V2,112,59,16);
    cudaEventRecord(evJ2,sB);

    k_conv16_3<<<(V1/4+TPB-1)/TPB,TPB>>>(ctx16,w1_[4],b1_[4],vel,D1,H1,W1);

    // ---- fine chain ----
    k_resize_up<<<GB2,TPB>>>(vel,velup,3,2.0f);
    k_warp<<<GB2,TPB>>>(dispup,velup,disp2,3,D2,H2,W2,1);
    k_warp<<<GB2,TPB>>>(fxu,disp2,wxu,16,D2,H2,W2,0);
    cudaEventRecord(evC,0);
    cudaStreamWaitEvent(sB,evC,0);
    k_pack_hl_t<<<V2/64,256,0,sB>>>(wxu,  xh2,xl2,V2,112,43,16);
    k_pack_hl_t<<<V2/64,256,0,sB>>>(disp2,xh2,xl2,V2,112,75,3);
    cudaEventRecord(evJ3,sB);

    k_zero_red<<<1,4>>>();
    k_reduce4<<<1024,256>>>((const float4*)wxu,4*V2,0);
    k_reduce4<<<1024,256>>>((const float4*)fyu,4*V2,2);
    k_finalize_ms<<<1,1>>>((double)(16*V2));
    {
        int nq=D2*H2*(W2/4);
        k_costvol4<1><<<dim3((nq+127)/128,3),128>>>(fyu,wxu,cv2,16,D2,H2,W2);
    }
    k_pack_hl_t<<<V2/64,256>>>(cv2,  xh2,xl2,V2,112,0, 27);

    cudaStreamWaitEvent(0,evJ2,0);
    cudaStreamWaitEvent(0,evJ3,0);

    // fl2 dense block
    run_wconv<32>(xh2,xl2,wh+WOFF4,wl+WOFF4,b2_[0],xh2,xl2,nullptr,112,78,128,D2,H2,W2,78);
    run_wconv<16>(xh2,xl2,wh+WOFF5,wl+WOFF5,b2_[1],nullptr,nullptr,xout2,112,110,128,D2,H2,W2,0);
    k_conv16_3<<<(V2/4+TPB-1)/TPB,TPB>>>(xout2,w2_[2],b2_[2],velup2,D2,H2,W2);

    {
        int nq=D2*H2*(W2/4);
        k_final<<<(nq+TPB-1)/TPB,TPB>>>(disp2,velup2,dispup,t_ptr,outf);
    }
}

// round 15
// speedup vs baseline: 1.0714x; 1.0714x over previous
#include <cuda_runtime.h>
#include <cuda_bf16.h>
#include <math.h>
#include <stdint.h>

#define D1 48
#define H1 40
#define W1 48
#define V1 (D1*H1*W1)
#define D2 96
#define H2 80
#define W2 96
#define V2 (D2*H2*W2)

// fp32 scratch arena
constexpr size_t N_XIN1  = 368ull * V1;
constexpr size_t N_XIN2  = 110ull * V2;
constexpr size_t N_CTX   = 16ull  * V1;
constexpr size_t N_VEL   = 3ull   * V1;
constexpr size_t N_VELUP = 3ull   * V2;
constexpr size_t N_XOUT2 = 16ull  * V2;
constexpr size_t N_VELUP2= 3ull   * V2;
constexpr size_t O_XIN1=0, O_XIN2=O_XIN1+N_XIN1, O_CTX=O_XIN2+N_XIN2, O_VEL=O_CTX+N_CTX,
  O_VELUP=O_VEL+N_VEL, O_XOUT2=O_VELUP+N_VELUP, O_VELUP2=O_XOUT2+N_XOUT2;
constexpr size_t ARENA_TOTAL = O_VELUP2 + N_VELUP2;

__device__ float  g_arena[ARENA_TOTAL];
__device__ double g_red[4];
__device__ float  g_ms[2];

// interleaved bf16 hi/lo activation arenas: [voxel][Ctot]
__device__ __align__(16) __nv_bfloat16 g_xh1[(size_t)V1*368];
__device__ __align__(16) __nv_bfloat16 g_xl1[(size_t)V1*368];
__device__ __align__(16) __nv_bfloat16 g_xh2[(size_t)V2*112];
__device__ __align__(16) __nv_bfloat16 g_xl2[(size_t)V2*112];

// weights [tap][coutNT][cinPad] bf16 hi/lo
constexpr size_t WOFF0=0;
constexpr size_t WOFF1=WOFF0+27ull*64*256;
constexpr size_t WOFF2=WOFF1+27ull*48*320;
constexpr size_t WOFF3=WOFF2+27ull*32*384;
constexpr size_t WOFF4=WOFF3+27ull*16*384;
constexpr size_t WOFF5=WOFF4+27ull*32*128;
constexpr size_t WTOT =WOFF5+27ull*16*128;
__device__ __align__(16) __nv_bfloat16 g_wh[WTOT];
__device__ __align__(16) __nv_bfloat16 g_wl[WTOT];

#define SWZ(o) ((o) ^ (((o)>>3)&0x70))

// ---------- helpers ----------
__device__ __forceinline__ uint32_t smem_u32(const void* p){
    uint32_t a; asm("{ .reg .u64 t; cvta.to.shared.u64 t, %1; cvt.u32.u64 %0, t; }":"=r"(a):"l"(p)); return a;
}
__device__ __forceinline__ void ldsm4(uint32_t* r, uint32_t addr){
    asm volatile("ldmatrix.sync.aligned.m8n8.x4.shared.b16 {%0,%1,%2,%3},[%4];"
        : "=r"(r[0]),"=r"(r[1]),"=r"(r[2]),"=r"(r[3]) : "r"(addr));
}
__device__ __forceinline__ void mma16816(float* c, const uint32_t* a, const uint32_t* b){
    asm volatile("mma.sync.aligned.m16n8k16.row.col.f32.bf16.bf16.f32 "
        "{%0,%1,%2,%3},{%4,%5,%6,%7},{%8,%9},{%0,%1,%2,%3};"
        : "+f"(c[0]),"+f"(c[1]),"+f"(c[2]),"+f"(c[3])
        : "r"(a[0]),"r"(a[1]),"r"(a[2]),"r"(a[3]),"r"(b[0]),"r"(b[1]));
}
__device__ __forceinline__ void split_hl(float v,__nv_bfloat16& h,__nv_bfloat16& l){
    h=__float2bfloat16(v);
    l=__float2bfloat16(v-__bfloat162float(h));
}
__device__ __forceinline__ void cpasync16(uint32_t saddr, const void* g){
    asm volatile("cp.async.cg.shared.global [%0], [%1], 16;"::"r"(saddr),"l"(g):"memory");
}
#define CP_COMMIT() asm volatile("cp.async.commit_group;":::"memory")
#define CP_WAIT1()  asm volatile("cp.async.wait_group 1;":::"memory")
#define CP_WAIT0()  asm volatile("cp.async.wait_group 0;":::"memory")

// ---------- small kernels ----------
__global__ void k_zero_red(){ if(threadIdx.x<4) g_red[threadIdx.x]=0.0; }
__global__ void k_reduce4(const float4* __restrict__ x,int n4,int slot){
    __shared__ double ss[256],sq[256];
    double s=0,q=0;
    for(int i=blockIdx.x*blockDim.x+threadIdx.x;i<n4;i+=gridDim.x*blockDim.x){
        float4 v=x[i];
        double a=v.x,b=v.y,c=v.z,d=v.w;
        s+=a+b+c+d; q+=a*a+b*b+c*c+d*d;
    }
    int t=threadIdx.x; ss[t]=s; sq[t]=q; __syncthreads();
    for(int o=128;o>0;o>>=1){ if(t<o){ss[t]+=ss[t+o];sq[t]+=sq[t+o];} __syncthreads(); }
    if(t==0){ atomicAdd(&g_red[slot],ss[0]); atomicAdd(&g_red[slot+1],sq[0]); }
}
__global__ void k_finalize_ms(double n){
    double ma=g_red[0]/n, mb=g_red[2]/n;
    double va=(g_red[1]-g_red[0]*g_red[0]/n)/(n-1.0), vb=(g_red[3]-g_red[2]*g_red[2]/n)/(n-1.0);
    double s=0.5*(sqrt(va)+sqrt(vb));
    g_ms[0]=(float)(0.5*(ma+mb)); g_ms[1]=(float)(1.0/s);
}
// fp32 channel-major -> hi/lo interleaved, tiled transpose
__global__ void k_pack_hl_t(const float* __restrict__ src,__nv_bfloat16* __restrict__ dh,
                            __nv_bfloat16* __restrict__ dl,size_t Vn,int Ctot,int c0,int nc){
    __shared__ float s[64*128];
    const size_t v0=(size_t)blockIdx.x*64;
    const int tid=threadIdx.x;
    for(int idx=tid;idx<nc*64;idx+=256){
        int c=idx>>6, j=idx&63;
        s[c*64+j]=src[(size_t)c*Vn+v0+j];
    }
    __syncthreads();
    const int tot=64*nc;
    for(int idx=tid;idx<tot;idx+=256){
        int vox=idx/nc, c=idx-vox*nc;
        float v=s[c*64+vox];
        __nv_bfloat16 h,l; split_hl(v,h,l);
        size_t o=(v0+vox)*(size_t)Ctot+c0+c;
        dh[o]=h; dl[o]=l;
    }
}
__global__ void k_prep_w(const float* __restrict__ src,__nv_bfloat16* __restrict__ dh,
                         __nv_bfloat16* __restrict__ dl,int Cout,int NT,int Cin,int Cpad){
    int n=NT*Cpad*27;
    for(int e=blockIdx.x*blockDim.x+threadIdx.x;e<n;e+=gridDim.x*blockDim.x){
        int ci=e%Cpad, co=(e/Cpad)%NT, tap=e/(Cpad*NT);
        float v=(ci<Cin&&co<Cout)?src[((size_t)co*Cin+ci)*27+tap]:0.f;
        __nv_bfloat16 h,l; split_hl(v,h,l);
        size_t d=((size_t)tap*NT+co)*Cpad+ci; dh[d]=h; dl[d]=l;
    }
}

// ---------- warp / final ----------
__device__ __forceinline__ void corners(float cz,float cy,float cx,int D,int H,int W,int HW,
                                        int* idx,float* w8){
    float fz0=floorf(cz),fy0=floorf(cy),fx0=floorf(cx);
    int z0=(int)fz0,y0=(int)fy0,x0=(int)fx0;
    float fz=cz-fz0,fy=cy-fy0,fx=cx-fx0;
    float wz[2]={1.f-fz,fz},wy[2]={1.f-fy,fy},wx[2]={1.f-fx,fx};
    #pragma unroll
    for(int dz=0;dz<2;dz++)
    #pragma unroll
    for(int dy=0;dy<2;dy++)
    #pragma unroll
    for(int dx=0;dx<2;dx++){
        int zi=z0+dz,yi=y0+dy,xi=x0+dx;
        bool v=(zi>=0&&zi<D&&yi>=0&&yi<H&&xi>=0&&xi<W);
        int zc=min(max(zi,0),D-1),yc=min(max(yi,0),H-1),xc=min(max(xi,0),W-1);
        int k=dz*4+dy*2+dx;
        idx[k]=zc*HW+yc*W+xc; w8[k]=v?wz[dz]*wy[dy]*wx[dx]:0.f;
    }
}
__global__ void k_warp(const float* __restrict__ vol,const float* __restrict__ flow,
                       float* __restrict__ out,int C,int D,int H,int W,int addFlow){
    size_t V=(size_t)D*H*W; int HW=H*W;
    for(size_t p=blockIdx.x*(size_t)blockDim.x+threadIdx.x;p<V;p+=(size_t)gridDim.x*blockDim.x){
        int z=(int)(p/HW),r=(int)(p%HW),y=r/W,x=r%W;
        int idx[8]; float w8[8];
        corners(z+flow[p],y+flow[V+p],x+flow[2*V+p],D,H,W,HW,idx,w8);
        for(int c=0;c<C;c++){
            const float* vc=vol+(size_t)c*V; float a=0.f;
            #pragma unroll
            for(int k=0;k<8;k++) a+=w8[k]*vc[idx[k]];
            out[(size_t)c*V+p]=a+(addFlow?flow[(size_t)c*V+p]:0.f);
        }
    }
}
__global__ void k_final(const float* __restrict__ disp2,const float* __restrict__ vel2,
                        const float* __restrict__ dispup,const float* __restrict__ tptr,
                        float* __restrict__ out){
    const int D=D2,H=H2,W=W2,HW=H*W; const size_t V=(size_t)V2;
    float inv=1.f/(1.f-tptr[0]);
    const int Wq=W>>2, nquad=D*H*Wq;
    for(int q=blockIdx.x*blockDim.x+threadIdx.x;q<nquad;q+=gridDim.x*blockDim.x){
        int xb=(q%Wq)<<2; int r=q/Wq; int y=r%H; int z=r/H;
        size_t p=(size_t)z*HW+(size_t)y*W+xb;
        float4 fz4=*(const float4*)(vel2+p);
        float4 fy4=*(const float4*)(vel2+V+p);
        float4 fx4=*(const float4*)(vel2+2*V+p);
        float fzv[4]={fz4.x,fz4.y,fz4.z,fz4.w};
        float fyv[4]={fy4.x,fy4.y,fy4.z,fy4.w};
        float fxv[4]={fx4.x,fx4.y,fx4.z,fx4.w};
        float res[3][4];
        #pragma unroll
        for(int vx=0;vx<4;vx++){
            int idx[8]; float w8[8];
            corners(z+fzv[vx],y+fyv[vx],xb+vx+fxv[vx],D,H,W,HW,idx,w8);
            #pragma unroll
            for(int c=0;c<3;c++){
                const float* vc=disp2+(size_t)c*V; float a=0.f;
                #pragma unroll
                for(int k=0;k<8;k++) a+=w8[k]*vc[idx[k]];
                float flowc=(c==0)?fzv[vx]:((c==1)?fyv[vx]:fxv[vx]);
                res[c][vx]=(a+flowc-dispup[(size_t)c*V+p+vx])*inv;
            }
        }
        #pragma unroll
        for(int c=0;c<3;c++)
            *(float4*)(out+(size_t)c*V+p)=make_float4(res[c][0],res[c][1],res[c][2],res[c][3]);
    }
}

// ---------- resizes ----------
__device__ __forceinline__ int taps_down(int o,int n,int* ti,float* tw){
    const float raw[4]={1.f,3.f,3.f,1.f}; int m=0; float tot=0.f;
    #pragma unroll
    for(int k=0;k<4;k++){int t=2*o-1+k; if(t>=0&&t<n){ti[m]=t;tw[m]=raw[k];tot+=raw[k];m++;}}
    float inv=1.f/tot; for(int i=0;i<m;i++)tw[i]*=inv; return m;
}
__global__ void k_resize_down(const float* __restrict__ in,float* __restrict__ out,float scale){
    int n=3*V1;
    for(int idx=blockIdx.x*blockDim.x+threadIdx.x;idx<n;idx+=gridDim.x*blockDim.x){
        int c=idx/V1,p=idx%V1,z=p/(H1*W1),r=p%(H1*W1),y=r/W1,x=r%W1;
        int zi[4],yi[4],xi[4]; float zw[4],yw[4],xw[4];
        int mz=taps_down(z,D2,zi,zw),my=taps_down(y,H2,yi,yw),mx=taps_down(x,W2,xi,xw);
        const float* ic=in+(size_t)c*V2; float a=0.f;
        for(int iz=0;iz<mz;iz++)for(int iy=0;iy<my;iy++){
            float wzy=zw[iz]*yw[iy];
            const float* row=ic+(size_t)zi[iz]*(H2*W2)+yi[iy]*W2;
            for(int ix=0;ix<mx;ix++)a+=wzy*xw[ix]*row[xi[ix]];
        }
        out[idx]=a*scale;
    }
}
__device__ __forceinline__ void taps_up(int o,int n,int& i0,int& i1,float& w0,float& w1){
    int j=o>>1;
    if((o&1)==0){ if(j==0){i0=0;i1=0;w0=1.f;w1=0.f;} else {i0=j-1;i1=j;w0=0.25f;w1=0.75f;} }
    else { if(j+1>=n){i0=j;i1=j;w0=1.f;w1=0.f;} else {i0=j;i1=j+1;w0=0.75f;w1=0.25f;} }
}
__global__ void k_resize_up(const float* __restrict__ in,float* __restrict__ out,int C,float scale){
    size_t n=(size_t)C*V2;
    for(size_t idx=blockIdx.x*(size_t)blockDim.x+threadIdx.x;idx<n;idx+=(size_t)gridDim.x*blockDim.x){
        int c=(int)(idx/V2),p=(int)(idx%V2),z=p/(H2*W2),r=p%(H2*W2),y=r/W2,x=r%W2;
        int z0,z1,y0,y1,x0,x1; float wz0,wz1,wy0,wy1,wx0,wx1;
        taps_up(z,D1,z0,z1,wz0,wz1); taps_up(y,H1,y0,y1,wy0,wy1); taps_up(x,W1,x0,x1,wx0,wx1);
        const float* ic=in+(size_t)c*V1; const int HW=H1*W1;
        float a=wz0*(wy0*(wx0*ic[z0*HW+y0*W1+x0]+wx1*ic[z0*HW+y0*W1+x1])+
                     wy1*(wx0*ic[z0*HW+y1*W1+x0]+wx1*ic[z0*HW+y1*W1+x1]))+
                wz1*(wy0*(wx0*ic[z1*HW+y0*W1+x0]+wx1*ic[z1*HW+y0*W1+x1])+
                     wy1*(wx0*ic[z1*HW+y1*W1+x0]+wx1*ic[z1*HW+y1*W1+x1]));
        out[idx]=a*scale;
    }
}

// ---------- cost volume, 4 voxels/thread, fused pair-normalization ----------
template <int MD>
__global__ void __launch_bounds__(128)
k_costvol4(const float* __restrict__ f1,const float* __restrict__ f2,
           float* __restrict__ out,int C,int D,int H,int W){
    const int N=2*MD+1;
    const int NW=2*MD+4;
    size_t V=(size_t)D*H*W; const int HW=H*W;
    const int i=blockIdx.y;
    const float invC=1.f/(float)C;
    const float m=g_ms[0], is=g_ms[1];
    const int Wq=W>>2;
    const int nquad=D*H*Wq;
    for(int q=blockIdx.x*blockDim.x+threadIdx.x;q<nquad;q+=gridDim.x*blockDim.x){
        int xb=(q%Wq)<<2; int r=q/Wq; int y=r%H; int z=r/H;
        size_t p=(size_t)z*HW+(size_t)y*W+xb;
        float acc[N*N][4];
        #pragma unroll
        for(int t=0;t<N*N;t++)
        #pragma unroll
        for(int vx=0;vx<4;vx++) acc[t][vx]=0.f;
        int zq=z+i-MD;
        if(zq>=0&&zq<D){
            for(int c=0;c<C;c++){
                float4 f1v=*(const float4*)(f1+(size_t)c*V+p);
                float tv[4]={(f1v.x-m)*is,(f1v.y-m)*is,(f1v.z-m)*is,(f1v.w-m)*is};
                const float* base=f2+(size_t)c*V+(size_t)zq*HW;
                #pragma unroll
                for(int j=0;j<N;j++){
                    int yq=y+j-MD; if(yq<0||yq>=H)continue;
                    const float* row=base+yq*W;
                    float v[NW];
                    float4 mm=*(const float4*)(row+xb);
                    v[MD+0]=(mm.x-m)*is; v[MD+1]=(mm.y-m)*is;
                    v[MD+2]=(mm.z-m)*is; v[MD+3]=(mm.w-m)*is;
                    if(MD==2){
                        if(xb>0){
                            float2 a2=*(const float2*)(row+xb-2);
                            v[0]=(a2.x-m)*is; v[1]=(a2.y-m)*is;
                        } else { v[0]=0.f; v[1]=0.f; }
                        if(xb+4<W){
                            float2 d2=*(const float2*)(row+xb+4);
                            v[6]=(d2.x-m)*is; v[7]=(d2.y-m)*is;
                        } else { v[6]=0.f; v[7]=0.f; }
                    } else {
                        v[0]=(xb>0)?(row[xb-1]-m)*is:0.f;
                        v[5]=(xb+4<W)?(row[xb+4]-m)*is:0.f;
                    }
                    #pragma unroll
                    for(int k=0;k<N;k++)
                    #pragma unroll
                    for(int vx=0;vx<4;vx++)
                        acc[j*N+k][vx]+=tv[vx]*v[vx+k];
                }
            }
        }
        #pragma unroll
        for(int j=0;j<N;j++)
        #pragma unroll
        for(int k=0;k<N;k++){
            float4 o;
            float* ap=acc[j*N+k];
            float a0=ap[0]*invC, a1=ap[1]*invC, a2=ap[2]*invC, a3=ap[3]*invC;
            o.x=(a0>=0.f)?a0:0.05f*a0;
            o.y=(a1>=0.f)?a1:0.05f*a1;
            o.z=(a2>=0.f)?a2:0.05f*a2;
            o.w=(a3>=0.f)?a3:0.05f*a3;
            *(float4*)(out+(size_t)((i*N+j)*N+k)*V+p)=o;
        }
    }
}

// ---------- unrolled per-tap MMA compute ----------
template<int KSN,int MF,int NB>
__device__ __forceinline__ void tap_compute(
    uint32_t sA_h,uint32_t sA_l,uint32_t sB_h,uint32_t sB_l,
    const uint32_t (&arow)[MF],int nbase,int bq,int bi,
    float (&acc)[MF][2*NB][4]){
    #pragma unroll
    for(int ks=0;ks<KSN;ks++){
        uint32_t ah[MF][4], al[MF][4];
        #pragma unroll
        for(int mf=0;mf<MF;mf++){
            uint32_t o=SWZ(arow[mf]+(uint32_t)ks*32);
            ldsm4(ah[mf],sA_h+o);
            ldsm4(al[mf],sA_l+o);
        }
        uint32_t bh[NB][4], bl[NB][4];
        #pragma unroll
        for(int g=0;g<NB;g++){
            int row=nbase+g*16+((bq>>1)<<3)+bi;
            uint32_t bo=SWZ((uint32_t)row*128+(uint32_t)(bq&1)*16+(uint32_t)ks*32);
            ldsm4(bh[g],sB_h+bo);
            ldsm4(bl[g],sB_l+bo);
        }
        #pragma unroll
        for(int mf=0;mf<MF;mf++)
        #pragma unroll
        for(int g=0;g<NB;g++)
        #pragma unroll
        for(int h=0;h<2;h++){
            float* C=acc[mf][g*2+h];
            mma16816(C,ah[mf],&bh[g][2*h]);
            mma16816(C,ah[mf],&bl[g][2*h]);
            mma16816(C,al[mf],&bh[g][2*h]);
        }
    }
}

// ---------- mma.sync implicit-GEMM conv (3x3x3 SAME), hi/lo bf16 ----------
// NT<=32: double-buffered cp.async B staging (latency hidden behind compute).
template<int NT>
__global__ void __launch_bounds__(256,2)
k_wmma_conv(const __nv_bfloat16* __restrict__ xh,const __nv_bfloat16* __restrict__ xl,
            const __nv_bfloat16* __restrict__ wh,const __nv_bfloat16* __restrict__ wl,
            const float* __restrict__ bias,
            __nv_bfloat16* oh,__nv_bfloat16* ol,float* of32,
            int Ctot,int Cin,int Cpad,int Dd,int Hh,int Ww,int coutOff){
    constexpr int MF=(NT==64)?2:1;
    constexpr int NF=(NT==64)?4:(NT/8);
    constexpr int NB=NF/2;
    constexpr bool DB=(NT<=32);
    constexpr uint32_t NTB=(uint32_t)NT*128;
    extern __shared__ __align__(128) char sm[];
    const uint32_t sA_h=smem_u32(sm);
    const uint32_t sA_l=sA_h+46080;
    const uint32_t sB0=sA_h+92160;

    const int tid=threadIdx.x, lane=tid&31, wid=tid>>5;
    const int x0=blockIdx.x*8, y0=blockIdx.y*4, z0=blockIdx.z*4;
    const int HW=Hh*Ww; const size_t V=(size_t)Dd*HW;
    const int mbase=(NT==64)?(wid&3)*32:wid*16;
    const int nbase=(NT==64)?(wid>>2)*32:0;

    float acc[MF][NF][4];
    #pragma unroll
    for(int a=0;a<MF;a++)
    #pragma unroll
    for(int b=0;b<NF;b++)
    #pragma unroll
    for(int c=0;c<4;c++) acc[a][b][c]=0.f;

    int lmx[MF],lmy[MF],lmz[MF];
    #pragma unroll
    for(int mf=0;mf<MF;mf++){
        int m=mbase+mf*16+(lane&15);
        lmx[mf]=m&7; lmy[mf]=(m>>3)&3; lmz[mf]=m>>5;
    }
    const uint32_t khoff=(uint32_t)(lane>>4)*16;
    const int bq=lane>>3, bi=lane&7;

    const int nchunk=(Cin+63)>>6;
    for(int ch=0;ch<nchunk;ch++){
        const int ci0=ch<<6;
        const int kreal=min(64,Cin-ci0);
        const int ksn=(kreal+15)>>4;
        const int nseg=2*ksn;
        __syncthreads();
        // ---- stage A halo ----
        for(int r=tid;r<360;r+=256){
            int hx=r%10, hy=(r/10)%6, hz=r/60;
            int gx=x0+hx-1, gy=y0+hy-1, gz=z0+hz-1;
            bool val=(gx>=0&&gx<Ww&&gy>=0&&gy<Hh&&gz>=0&&gz<Dd);
            size_t vox=val?((size_t)gz*HW+(size_t)gy*Ww+gx):0;
            const __nv_bfloat16* ph=xh+vox*(size_t)Ctot+ci0;
            const __nv_bfloat16* pl=xl+vox*(size_t)Ctot+ci0;
            uint32_t rb=(uint32_t)r*128;
            for(int s=0;s<nseg;s++){
                uint4 vh=make_uint4(0,0,0,0), vl=make_uint4(0,0,0,0);
                if(val){
                    if(s*8+8<=kreal){ vh=*(const uint4*)(ph+s*8); vl=*(const uint4*)(pl+s*8); }
                    else if(s*8<kreal){
                        uint16_t th[8]={0,0,0,0,0,0,0,0}, tl[8]={0,0,0,0,0,0,0,0};
                        for(int j=0;j<8;j++) if(s*8+j<kreal){
                            th[j]=((const uint16_t*)ph)[s*8+j];
                            tl[j]=((const uint16_t*)pl)[s*8+j];
                        }
                        vh=*(uint4*)th; vl=*(uint4*)tl;
                    }
                }
                uint32_t off=SWZ(rb+(uint32_t)s*16);
                *(uint4*)(sm+off)=vh;
                *(uint4*)(sm+46080+off)=vl;
            }
        }
        if(DB){
            // prefetch tap 0's B into buffer 0 (buf0's prior readers done at chunk-top sync)
            for(int s=tid;s<NT*nseg;s+=256){
                int n=s/nseg, seg=s-n*nseg;
                size_t wb=((size_t)0*NT+n)*Cpad+ci0+seg*8;
                uint32_t off=SWZ((uint32_t)n*128+(uint32_t)seg*16);
                cpasync16(sB0+off,wh+wb);
                cpasync16(sB0+NTB+off,wl+wb);
            }
            CP_COMMIT();
        }
        // ---- taps ----
        for(int tap=0;tap<27;tap++){
            __syncthreads();   // prior compute done (protects A on first iter, B buffers after)
            uint32_t sBh,sBl;
            if(DB){
                if(tap<26){
                    uint32_t nb_=sB0+(uint32_t)(((tap+1)&1)*2)*NTB;
                    for(int s=tid;s<NT*nseg;s+=256){
                        int n=s/nseg, seg=s-n*nseg;
                        size_t wb=((size_t)(tap+1)*NT+n)*Cpad+ci0+seg*8;
                        uint32_t off=SWZ((uint32_t)n*128+(uint32_t)seg*16);
                        cpasync16(nb_+off,wh+wb);
                        cpasync16(nb_+NTB+off,wl+wb);
                    }
                    CP_COMMIT();
                    CP_WAIT1();
                } else {
                    CP_WAIT0();
                }
                sBh=sB0+(uint32_t)((tap&1)*2)*NTB;
                sBl=sBh+NTB;
            } else {
                for(int s=tid;s<NT*nseg;s+=256){
                    int n=s/nseg, seg=s-n*nseg;
                    size_t wb=((size_t)tap*NT+n)*Cpad+ci0+seg*8;
                    uint32_t off=SWZ((uint32_t)n*128+(uint32_t)seg*16);
                    *(uint4*)(sm+92160+off)=*(const uint4*)(wh+wb);
                    *(uint4*)(sm+92160+NTB+off)=*(const uint4*)(wl+wb);
                }
                sBh=sB0; sBl=sB0+NTB;
            }
            __syncthreads();   // B (and A) visible to all threads
            const int dz=tap/9-1, dy=(tap/3)%3-1, dx=tap%3-1;
            uint32_t arow[MF];
            #pragma unroll
            for(int mf=0;mf<MF;mf++){
                int hr=((lmz[mf]+dz+1)*6+(lmy[mf]+dy+1))*10+(lmx[mf]+dx+1);
                arow[mf]=(uint32_t)hr*128+khoff;
            }
            switch(ksn){
                case 4: tap_compute<4,MF,NB>(sA_h,sA_l,sBh,sBl,arow,nbase,bq,bi,acc); break;
                case 3: tap_compute<3,MF,NB>(sA_h,sA_l,sBh,sBl,arow,nbase,bq,bi,acc); break;
                case 2: tap_compute<2,MF,NB>(sA_h,sA_l,sBh,sBl,arow,nbase,bq,bi,acc); break;
                default: tap_compute<1,MF,NB>(sA_h,sA_l,sBh,sBl,arow,nbase,bq,bi,acc); break;
            }
        }
    }

    // ---- epilogue ----
    #pragma unroll
    for(int mf=0;mf<MF;mf++)
    #pragma unroll
    for(int nf=0;nf<NF;nf++)
    #pragma unroll
    for(int rp=0;rp<2;rp++){
        int m=mbase+mf*16+(lane>>2)+rp*8;
        int n=nbase+nf*8+((lane&3)<<1);
        int gx=x0+(m&7), gy=y0+((m>>3)&3), gz=z0+(m>>5);
        size_t vox=(size_t)gz*HW+(size_t)gy*Ww+gx;
        float v0=acc[mf][nf][rp*2+0]+bias[n];
        float v1=acc[mf][nf][rp*2+1]+bias[n+1];
        v0=(v0>=0.f)?v0:0.02f*v0;
        v1=(v1>=0.f)?v1:0.02f*v1;
        if(oh!=nullptr){
            __nv_bfloat16 h0,l0,h1,l1;
            split_hl(v0,h0,l0); split_hl(v1,h1,l1);
            uint32_t ph_=(uint32_t)__bfloat16_as_ushort(h0)|((uint32_t)__bfloat16_as_ushort(h1)<<16);
            uint32_t pl_=(uint32_t)__bfloat16_as_ushort(l0)|((uint32_t)__bfloat16_as_ushort(l1)<<16);
            *(uint32_t*)(oh+vox*(size_t)Ctot+coutOff+n)=ph_;
            *(uint32_t*)(ol+vox*(size_t)Ctot+coutOff+n)=pl_;
        }
        if(of32!=nullptr){
            of32[(size_t)n*V+vox]=v0;
            of32[(size_t)(n+1)*V+vox]=v1;
        }
    }
}

// ---------- SIMT conv 16->3, 4 voxels/thread ----------
__global__ void k_conv16_3(const float* __restrict__ in,const float* __restrict__ wg,
                           const float* __restrict__ bias,float* __restrict__ out,
                           int Dd,int Hh,int Ww){
    __shared__ float sw[1296]; __shared__ float sb[3];
    int tid=threadIdx.x;
    for(int l=tid;l<1296;l+=blockDim.x)sw[l]=wg[l];
    if(tid<3)sb[tid]=bias[tid];
    __syncthreads();
    const int HW=Hh*Ww; const size_t V=(size_t)Dd*HW;
    const int Wq=Ww>>2;
    const int nquad=Dd*Hh*Wq;
    for(int q=blockIdx.x*blockDim.x+tid;q<nquad;q+=gridDim.x*blockDim.x){
        int xq=q%Wq; int r=q/Wq; int y=r%Hh; int z=r/Hh;
        int xb=xq<<2;
        float a[3][4];
        #pragma unroll
        for(int o=0;o<3;o++)
        #pragma unroll
        for(int j=0;j<4;j++) a[o][j]=sb[o];
        for(int dz=-1;dz<=1;dz++){
            int zz=z+dz; if(zz<0||zz>=Dd)continue;
            for(int dy=-1;dy<=1;dy++){
                int yy=y+dy; if(yy<0||yy>=Hh)continue;
                int tap0=(dz+1)*9+(dy+1)*3;
                #pragma unroll 2
                for(int c=0;c<16;c++){
                    const float* row=in+(size_t)c*V+(size_t)zz*HW+(size_t)yy*Ww+xb;
                    float v[6];
                    float4 mid=*(const float4*)row;
                    v[1]=mid.x; v[2]=mid.y; v[3]=mid.z; v[4]=mid.w;
                    v[0]=(xb>0)?row[-1]:0.f;
                    v[5]=(xb+4<Ww)?row[4]:0.f;
                    #pragma unroll
                    for(int dx=0;dx<3;dx++){
                        float w0=sw[c*27+tap0+dx];
                        float w1=sw[(16+c)*27+tap0+dx];
                        float w2=sw[(32+c)*27+tap0+dx];
                        #pragma unroll
                        for(int j=0;j<4;j++){
                            float vv=v[j+dx];
                            a[0][j]+=vv*w0; a[1][j]+=vv*w1; a[2][j]+=vv*w2;
                        }
                    }
                }
            }
        }
        size_t p=(size_t)z*HW+(size_t)y*Ww+xb;
        #pragma unroll
        for(int o=0;o<3;o++)
            *(float4*)(out+(size_t)o*V+p)=make_float4(a[o][0],a[o][1],a[o][2],a[o][3]);
    }
}

// ---------- host ----------
template<int NT>
static void run_wconv(const __nv_bfloat16* xh,const __nv_bfloat16* xl,
                      const __nv_bfloat16* wh,const __nv_bfloat16* wl,const float* bias,
                      __nv_bfloat16* oh,__nv_bfloat16* ol,float* of32,
                      int Ctot,int Cin,int Cpad,int Dd,int Hh,int Ww,int coutOff){
    size_t smv=92160+((NT<=32)?4:2)*(size_t)NT*128;
    cudaFuncSetAttribute(k_wmma_conv<NT>,cudaFuncAttributeMaxDynamicSharedMemorySize,(int)smv);
    dim3 g(Ww/8,Hh/4,Dd/4);
    k_wmma_conv<NT><<<g,256,smv>>>(xh,xl,wh,wl,bias,oh,ol,of32,Ctot,Cin,Cpad,Dd,Hh,Ww,coutOff);
}

extern "C" void kernel_launch(void* const* d_in,const int* in_sizes,int n_in,
                              void* d_out,int out_size){
    const float* t_ptr=(const float*)d_in[0];
    const float* dispup=(const float*)d_in[1];
    const float* fx=(const float*)d_in[2];
    const float* fy=(const float*)d_in[3];
    const float* fxu=(const float*)d_in[4];
    const float* fyu=(const float*)d_in[5];
    const float* ctx=(const float*)d_in[6];
    const float* w1_[5]={(const float*)d_in[7],(const float*)d_in[9],(const float*)d_in[11],
                         (const float*)d_in[13],(const float*)d_in[15]};
    const float* b1_[5]={(const float*)d_in[8],(const float*)d_in[10],(const float*)d_in[12],
                         (const float*)d_in[14],(const float*)d_in[16]};
    const float* w2_[3]={(const float*)d_in[17],(const float*)d_in[19],(const float*)d_in[21]};
    const float* b2_[3]={(const float*)d_in[18],(const float*)d_in[20],(const float*)d_in[22]};

    float* A; cudaGetSymbolAddress((void**)&A,g_arena);
    __nv_bfloat16 *xh1,*xl1,*xh2,*xl2,*wh,*wl;
    cudaGetSymbolAddress((void**)&xh1,g_xh1); cudaGetSymbolAddress((void**)&xl1,g_xl1);
    cudaGetSymbolAddress((void**)&xh2,g_xh2); cudaGetSymbolAddress((void**)&xl2,g_xl2);
    cudaGetSymbolAddress((void**)&wh,g_wh);   cudaGetSymbolAddress((void**)&wl,g_wl);

    float* xin1=A+O_XIN1;  float* xin2=A+O_XIN2;
    float* ctx16=A+O_CTX;  float* vel=A+O_VEL;   float* velup=A+O_VELUP;
    float* xout2=A+O_XOUT2;float* velup2=A+O_VELUP2;
    float* cv1=xin1;                  float* wx=xin1+157ull*V1;  float* disp=xin1+221ull*V1;
    float* cv2=xin2;                  float* wxu=xin2+43ull*V2;
    float* upctx=xin2+59ull*V2;       float* disp2=xin2+75ull*V2;
    float* outf=(float*)d_out;

    static cudaStream_t sB=nullptr;
    static cudaEvent_t evF=nullptr,evA=nullptr,evJ1=nullptr,
                       evB=nullptr,evJ2=nullptr,evC=nullptr,evJ3=nullptr;
    if(sB==nullptr){
        cudaStreamCreateWithFlags(&sB,cudaStreamNonBlocking);
        cudaEventCreateWithFlags(&evF,cudaEventDisableTiming);
        cudaEventCreateWithFlags(&evA,cudaEventDisableTiming);
        cudaEventCreateWithFlags(&evJ1,cudaEventDisableTiming);
        cudaEventCreateWithFlags(&evB,cudaEventDisableTiming);
        cudaEventCreateWithFlags(&evJ2,cudaEventDisableTiming);
        cudaEventCreateWithFlags(&evC,cudaEventDisableTiming);
        cudaEventCreateWithFlags(&evJ3,cudaEventDisableTiming);
    }

    const int TPB=256, GB1=(V1+TPB-1)/TPB, GB2=(V2+TPB-1)/TPB;
    cudaMemsetAsync(d_out,0,(size_t)out_size*sizeof(float),0);

    // ---- fork 0: weight prep + true-input packs ----
    cudaEventRecord(evF,0);
    cudaStreamWaitEvent(sB,evF,0);
    k_prep_w<<<512,256,0,sB>>>(w1_[0],wh+WOFF0,wl+WOFF0,64,64,224,256);
    k_prep_w<<<512,256,0,sB>>>(w1_[1],wh+WOFF1,wl+WOFF1,48,48,288,320);
    k_prep_w<<<512,256,0,sB>>>(w1_[2],wh+WOFF2,wl+WOFF2,32,32,336,384);
    k_prep_w<<<512,256,0,sB>>>(w1_[3],wh+WOFF3,wl+WOFF3,16,16,368,384);
    k_prep_w<<<256,256,0,sB>>>(w2_[0],wh+WOFF4,wl+WOFF4,32,32,78,128);
    k_prep_w<<<256,256,0,sB>>>(w2_[1],wh+WOFF5,wl+WOFF5,16,16,110,128);
    k_pack_hl_t<<<V1/64,256,0,sB>>>(fy,  xh1,xl1,V1,368,125,32);
    k_pack_hl_t<<<V1/64,256,0,sB>>>(ctx, xh1,xl1,V1,368,189,32);
    k_pack_hl_t<<<V2/64,256,0,sB>>>(fyu, xh2,xl2,V2,112,27,16);

    // ---- coarse chain ----
    k_resize_down<<<(3*V1+TPB-1)/TPB,TPB>>>(dispup,disp,0.5f);
    k_warp<<<GB1,TPB>>>(fx,disp,wx,32,D1,H1,W1,0);
    cudaEventRecord(evA,0);
    cudaStreamWaitEvent(sB,evA,0);
    k_pack_hl_t<<<V1/64,256,0,sB>>>(wx,  xh1,xl1,V1,368,157,32);
    k_pack_hl_t<<<V1/64,256,0,sB>>>(disp,xh1,xl1,V1,368,221,3);
    cudaEventRecord(evJ1,sB);

    k_zero_red<<<1,4>>>();
    k_reduce4<<<1024,256>>>((const float4*)wx,8*V1,0);
    k_reduce4<<<1024,256>>>((const float4*)fy,8*V1,2);
    k_finalize_ms<<<1,1>>>((double)(32*V1));
    {
        int nq=D1*H1*(W1/4);
        k_costvol4<2><<<dim3((nq+127)/128,5),128>>>(fy,wx,cv1,32,D1,H1,W1);
    }
    k_pack_hl_t<<<V1/64,256>>>(cv1, xh1,xl1,V1,368,0,  125);

    cudaStreamWaitEvent(0,evJ1,0);

    // fl1 dense block
    run_wconv<64>(xh1,xl1,wh+WOFF0,wl+WOFF0,b1_[0],xh1,xl1,nullptr,368,224,256,D1,H1,W1,224);
    run_wconv<48>(xh1,xl1,wh+WOFF1,wl+WOFF1,b1_[1],xh1,xl1,nullptr,368,288,320,D1,H1,W1,288);
    run_wconv<32>(xh1,xl1,wh+WOFF2,wl+WOFF2,b1_[2],xh1,xl1,nullptr,368,336,384,D1,H1,W1,336);
    run_wconv<16>(xh1,xl1,wh+WOFF3,wl+WOFF3,b1_[3],nullptr,nullptr,ctx16,368,368,384,D1,H1,W1,0);
    cudaEventRecord(evB,0);
    cudaStreamWaitEvent(sB,evB,0);
    k_resize_up<<<GB2*2,256,0,sB>>>(ctx16,upctx,16,1.0f);
    k_pack_hl_t<<<V2/64,256,0,sB>>>(upctx,xh2,xl2,V2,112,59,16);
    cudaEventRecord(evJ2,sB);

    k_conv16_3<<<(V1/4+TPB-1)/TPB,TPB>>>(ctx16,w1_[4],b1_[4],vel,D1,H1,W1);

    // ---- fine chain ----
    k_resize_up<<<GB2,TPB>>>(vel,velup,3,2.0f);
    k_warp<<<GB2,TPB>>>(dispup,velup,disp2,3,D2,H2,W2,1);
    k_warp<<<GB2,TPB>>>(fxu,disp2,wxu,16,D2,H2,W2,0);
    cudaEventRecord(evC,0);
    cudaStreamWaitEvent(sB,evC,0);
    k_pack_hl_t<<<V2/64,256,0,sB>>>(wxu,  xh2,xl2,V2,112,43,16);
    k_pack_hl_t<<<V2/64,256,0,sB>>>(disp2,xh2,xl2,V2,112,75,3);
    cudaEventRecord(evJ3,sB);

    k_zero_red<<<1,4>>>();
    k_reduce4<<<1024,256>>>((const float4*)wxu,4*V2,0);
    k_reduce4<<<1024,256>>>((const float4*)fyu,4*V2,2);
    k_finalize_ms<<<1,1>>>((double)(16*V2));
    {
        int nq=D2*H2*(W2/4);
        k_costvol4<1><<<dim3((nq+127)/128,3),128>>>(fyu,wxu,cv2,16,D2,H2,W2);
    }
    k_pack_hl_t<<<V2/64,256>>>(cv2,  xh2,xl2,V2,112,0, 27);

    cudaStreamWaitEvent(0,evJ2,0);
    cudaStreamWaitEvent(0,evJ3,0);

    // fl2 dense block
    run_wconv<32>(xh2,xl2,wh+WOFF4,wl+WOFF4,b2_[0],xh2,xl2,nullptr,112,78,128,D2,H2,W2,78);
    run_wconv<16>(xh2,xl2,wh+WOFF5,wl+WOFF5,b2_[1],nullptr,nullptr,xout2,112,110,128,D2,H2,W2,0);
    k_conv16_3<<<(V2/4+TPB-1)/TPB,TPB>>>(xout2,w2_[2],b2_[2],velup2,D2,H2,W2);

    {
        int nq=D2*H2*(W2/4);
        k_final<<<(nq+TPB-1)/TPB,TPB>>>(disp2,velup2,dispup,t_ptr,outf);
    }
}

// round 16
// speedup vs baseline: 1.1001x; 1.0268x over previous
#include <cuda_runtime.h>
#include <cuda_bf16.h>
#include <math.h>
#include <stdint.h>

#define D1 48
#define H1 40
#define W1 48
#define V1 (D1*H1*W1)
#define D2 96
#define H2 80
#define W2 96
#define V2 (D2*H2*W2)

// fp32 scratch arena
constexpr size_t N_XIN1  = 368ull * V1;
constexpr size_t N_XIN2  = 110ull * V2;
constexpr size_t N_CTX   = 16ull  * V1;
constexpr size_t N_VEL   = 3ull   * V1;
constexpr size_t N_VELUP = 3ull   * V2;
constexpr size_t N_XOUT2 = 16ull  * V2;
constexpr size_t N_VELUP2= 3ull   * V2;
constexpr size_t O_XIN1=0, O_XIN2=O_XIN1+N_XIN1, O_CTX=O_XIN2+N_XIN2, O_VEL=O_CTX+N_CTX,
  O_VELUP=O_VEL+N_VEL, O_XOUT2=O_VELUP+N_VELUP, O_VELUP2=O_XOUT2+N_XOUT2;
constexpr size_t ARENA_TOTAL = O_VELUP2 + N_VELUP2;

__device__ float  g_arena[ARENA_TOTAL];
__device__ double g_red[4];
__device__ float  g_ms[2];

// interleaved bf16 hi/lo activation arenas: [voxel][Ctot]
__device__ __align__(16) __nv_bfloat16 g_xh1[(size_t)V1*368];
__device__ __align__(16) __nv_bfloat16 g_xl1[(size_t)V1*368];
__device__ __align__(16) __nv_bfloat16 g_xh2[(size_t)V2*112];
__device__ __align__(16) __nv_bfloat16 g_xl2[(size_t)V2*112];

// weights [tap][coutNT][cinPad] bf16 hi/lo
constexpr size_t WOFF0=0;
constexpr size_t WOFF1=WOFF0+27ull*64*256;
constexpr size_t WOFF2=WOFF1+27ull*48*320;
constexpr size_t WOFF3=WOFF2+27ull*32*384;
constexpr size_t WOFF4=WOFF3+27ull*16*384;
constexpr size_t WOFF5=WOFF4+27ull*32*128;
constexpr size_t WTOT =WOFF5+27ull*16*128;
__device__ __align__(16) __nv_bfloat16 g_wh[WTOT];
__device__ __align__(16) __nv_bfloat16 g_wl[WTOT];

#define SWZ(o) ((o) ^ (((o)>>3)&0x70))

// ---------- helpers ----------
__device__ __forceinline__ uint32_t smem_u32(const void* p){
    uint32_t a; asm("{ .reg .u64 t; cvta.to.shared.u64 t, %1; cvt.u32.u64 %0, t; }":"=r"(a):"l"(p)); return a;
}
__device__ __forceinline__ void ldsm4(uint32_t* r, uint32_t addr){
    asm volatile("ldmatrix.sync.aligned.m8n8.x4.shared.b16 {%0,%1,%2,%3},[%4];"
        : "=r"(r[0]),"=r"(r[1]),"=r"(r[2]),"=r"(r[3]) : "r"(addr));
}
__device__ __forceinline__ void mma16816(float* c, const uint32_t* a, const uint32_t* b){
    asm volatile("mma.sync.aligned.m16n8k16.row.col.f32.bf16.bf16.f32 "
        "{%0,%1,%2,%3},{%4,%5,%6,%7},{%8,%9},{%0,%1,%2,%3};"
        : "+f"(c[0]),"+f"(c[1]),"+f"(c[2]),"+f"(c[3])
        : "r"(a[0]),"r"(a[1]),"r"(a[2]),"r"(a[3]),"r"(b[0]),"r"(b[1]));
}
__device__ __forceinline__ void split_hl(float v,__nv_bfloat16& h,__nv_bfloat16& l){
    h=__float2bfloat16(v);
    l=__float2bfloat16(v-__bfloat162float(h));
}
__device__ __forceinline__ void cpasync16(uint32_t saddr, const void* g){
    asm volatile("cp.async.cg.shared.global [%0], [%1], 16;"::"r"(saddr),"l"(g):"memory");
}
#define CP_COMMIT() asm volatile("cp.async.commit_group;":::"memory")
#define CP_WAIT1()  asm volatile("cp.async.wait_group 1;":::"memory")
#define CP_WAIT0()  asm volatile("cp.async.wait_group 0;":::"memory")

// ---------- small kernels ----------
__global__ void k_zero_red(){ if(threadIdx.x<4) g_red[threadIdx.x]=0.0; }
__global__ void k_reduce4(const float4* __restrict__ x,int n4,int slot){
    __shared__ double ss[256],sq[256];
    double s=0,q=0;
    for(int i=blockIdx.x*blockDim.x+threadIdx.x;i<n4;i+=gridDim.x*blockDim.x){
        float4 v=x[i];
        double a=v.x,b=v.y,c=v.z,d=v.w;
        s+=a+b+c+d; q+=a*a+b*b+c*c+d*d;
    }
    int t=threadIdx.x; ss[t]=s; sq[t]=q; __syncthreads();
    for(int o=128;o>0;o>>=1){ if(t<o){ss[t]+=ss[t+o];sq[t]+=sq[t+o];} __syncthreads(); }
    if(t==0){ atomicAdd(&g_red[slot],ss[0]); atomicAdd(&g_red[slot+1],sq[0]); }
}
__global__ void k_finalize_ms(double n){
    double ma=g_red[0]/n, mb=g_red[2]/n;
    double va=(g_red[1]-g_red[0]*g_red[0]/n)/(n-1.0), vb=(g_red[3]-g_red[2]*g_red[2]/n)/(n-1.0);
    double s=0.5*(sqrt(va)+sqrt(vb));
    g_ms[0]=(float)(0.5*(ma+mb)); g_ms[1]=(float)(1.0/s);
}
// fp32 channel-major -> hi/lo interleaved, tiled transpose
__global__ void k_pack_hl_t(const float* __restrict__ src,__nv_bfloat16* __restrict__ dh,
                            __nv_bfloat16* __restrict__ dl,size_t Vn,int Ctot,int c0,int nc){
    __shared__ float s[64*128];
    const size_t v0=(size_t)blockIdx.x*64;
    const int tid=threadIdx.x;
    for(int idx=tid;idx<nc*64;idx+=256){
        int c=idx>>6, j=idx&63;
        s[c*64+j]=src[(size_t)c*Vn+v0+j];
    }
    __syncthreads();
    const int tot=64*nc;
    for(int idx=tid;idx<tot;idx+=256){
        int vox=idx/nc, c=idx-vox*nc;
        float v=s[c*64+vox];
        __nv_bfloat16 h,l; split_hl(v,h,l);
        size_t o=(v0+vox)*(size_t)Ctot+c0+c;
        dh[o]=h; dl[o]=l;
    }
}
__global__ void k_prep_w(const float* __restrict__ src,__nv_bfloat16* __restrict__ dh,
                         __nv_bfloat16* __restrict__ dl,int Cout,int NT,int Cin,int Cpad){
    int n=NT*Cpad*27;
    for(int e=blockIdx.x*blockDim.x+threadIdx.x;e<n;e+=gridDim.x*blockDim.x){
        int ci=e%Cpad, co=(e/Cpad)%NT, tap=e/(Cpad*NT);
        float v=(ci<Cin&&co<Cout)?src[((size_t)co*Cin+ci)*27+tap]:0.f;
        __nv_bfloat16 h,l; split_hl(v,h,l);
        size_t d=((size_t)tap*NT+co)*Cpad+ci; dh[d]=h; dl[d]=l;
    }
}

// ---------- warp / final ----------
__device__ __forceinline__ void corners(float cz,float cy,float cx,int D,int H,int W,int HW,
                                        int* idx,float* w8){
    float fz0=floorf(cz),fy0=floorf(cy),fx0=floorf(cx);
    int z0=(int)fz0,y0=(int)fy0,x0=(int)fx0;
    float fz=cz-fz0,fy=cy-fy0,fx=cx-fx0;
    float wz[2]={1.f-fz,fz},wy[2]={1.f-fy,fy},wx[2]={1.f-fx,fx};
    #pragma unroll
    for(int dz=0;dz<2;dz++)
    #pragma unroll
    for(int dy=0;dy<2;dy++)
    #pragma unroll
    for(int dx=0;dx<2;dx++){
        int zi=z0+dz,yi=y0+dy,xi=x0+dx;
        bool v=(zi>=0&&zi<D&&yi>=0&&yi<H&&xi>=0&&xi<W);
        int zc=min(max(zi,0),D-1),yc=min(max(yi,0),H-1),xc=min(max(xi,0),W-1);
        int k=dz*4+dy*2+dx;
        idx[k]=zc*HW+yc*W+xc; w8[k]=v?wz[dz]*wy[dy]*wx[dx]:0.f;
    }
}
__global__ void k_warp(const float* __restrict__ vol,const float* __restrict__ flow,
                       float* __restrict__ out,int C,int D,int H,int W,int addFlow){
    size_t V=(size_t)D*H*W; int HW=H*W;
    for(size_t p=blockIdx.x*(size_t)blockDim.x+threadIdx.x;p<V;p+=(size_t)gridDim.x*blockDim.x){
        int z=(int)(p/HW),r=(int)(p%HW),y=r/W,x=r%W;
        int idx[8]; float w8[8];
        corners(z+flow[p],y+flow[V+p],x+flow[2*V+p],D,H,W,HW,idx,w8);
        for(int c=0;c<C;c++){
            const float* vc=vol+(size_t)c*V; float a=0.f;
            #pragma unroll
            for(int k=0;k<8;k++) a+=w8[k]*vc[idx[k]];
            out[(size_t)c*V+p]=a+(addFlow?flow[(size_t)c*V+p]:0.f);
        }
    }
}
__global__ void k_final(const float* __restrict__ disp2,const float* __restrict__ vel2,
                        const float* __restrict__ dispup,const float* __restrict__ tptr,
                        float* __restrict__ out){
    const int D=D2,H=H2,W=W2,HW=H*W; const size_t V=(size_t)V2;
    float inv=1.f/(1.f-tptr[0]);
    const int Wq=W>>2, nquad=D*H*Wq;
    for(int q=blockIdx.x*blockDim.x+threadIdx.x;q<nquad;q+=gridDim.x*blockDim.x){
        int xb=(q%Wq)<<2; int r=q/Wq; int y=r%H; int z=r/H;
        size_t p=(size_t)z*HW+(size_t)y*W+xb;
        float4 fz4=*(const float4*)(vel2+p);
        float4 fy4=*(const float4*)(vel2+V+p);
        float4 fx4=*(const float4*)(vel2+2*V+p);
        float fzv[4]={fz4.x,fz4.y,fz4.z,fz4.w};
        float fyv[4]={fy4.x,fy4.y,fy4.z,fy4.w};
        float fxv[4]={fx4.x,fx4.y,fx4.z,fx4.w};
        float res[3][4];
        #pragma unroll
        for(int vx=0;vx<4;vx++){
            int idx[8]; float w8[8];
            corners(z+fzv[vx],y+fyv[vx],xb+vx+fxv[vx],D,H,W,HW,idx,w8);
            #pragma unroll
            for(int c=0;c<3;c++){
                const float* vc=disp2+(size_t)c*V; float a=0.f;
                #pragma unroll
                for(int k=0;k<8;k++) a+=w8[k]*vc[idx[k]];
                float flowc=(c==0)?fzv[vx]:((c==1)?fyv[vx]:fxv[vx]);
                res[c][vx]=(a+flowc-dispup[(size_t)c*V+p+vx])*inv;
            }
        }
        #pragma unroll
        for(int c=0;c<3;c++)
            *(float4*)(out+(size_t)c*V+p)=make_float4(res[c][0],res[c][1],res[c][2],res[c][3]);
    }
}

// ---------- resizes ----------
__device__ __forceinline__ int taps_down(int o,int n,int* ti,float* tw){
    const float raw[4]={1.f,3.f,3.f,1.f}; int m=0; float tot=0.f;
    #pragma unroll
    for(int k=0;k<4;k++){int t=2*o-1+k; if(t>=0&&t<n){ti[m]=t;tw[m]=raw[k];tot+=raw[k];m++;}}
    float inv=1.f/tot; for(int i=0;i<m;i++)tw[i]*=inv; return m;
}
__global__ void k_resize_down(const float* __restrict__ in,float* __restrict__ out,float scale){
    int n=3*V1;
    for(int idx=blockIdx.x*blockDim.x+threadIdx.x;idx<n;idx+=gridDim.x*blockDim.x){
        int c=idx/V1,p=idx%V1,z=p/(H1*W1),r=p%(H1*W1),y=r/W1,x=r%W1;
        int zi[4],yi[4],xi[4]; float zw[4],yw[4],xw[4];
        int mz=taps_down(z,D2,zi,zw),my=taps_down(y,H2,yi,yw),mx=taps_down(x,W2,xi,xw);
        const float* ic=in+(size_t)c*V2; float a=0.f;
        for(int iz=0;iz<mz;iz++)for(int iy=0;iy<my;iy++){
            float wzy=zw[iz]*yw[iy];
            const float* row=ic+(size_t)zi[iz]*(H2*W2)+yi[iy]*W2;
            for(int ix=0;ix<mx;ix++)a+=wzy*xw[ix]*row[xi[ix]];
        }
        out[idx]=a*scale;
    }
}
__device__ __forceinline__ void taps_up(int o,int n,int& i0,int& i1,float& w0,float& w1){
    int j=o>>1;
    if((o&1)==0){ if(j==0){i0=0;i1=0;w0=1.f;w1=0.f;} else {i0=j-1;i1=j;w0=0.25f;w1=0.75f;} }
    else { if(j+1>=n){i0=j;i1=j;w0=1.f;w1=0.f;} else {i0=j;i1=j+1;w0=0.75f;w1=0.25f;} }
}
__global__ void k_resize_up(const float* __restrict__ in,float* __restrict__ out,int C,float scale){
    size_t n=(size_t)C*V2;
    for(size_t idx=blockIdx.x*(size_t)blockDim.x+threadIdx.x;idx<n;idx+=(size_t)gridDim.x*blockDim.x){
        int c=(int)(idx/V2),p=(int)(idx%V2),z=p/(H2*W2),r=p%(H2*W2),y=r/W2,x=r%W2;
        int z0,z1,y0,y1,x0,x1; float wz0,wz1,wy0,wy1,wx0,wx1;
        taps_up(z,D1,z0,z1,wz0,wz1); taps_up(y,H1,y0,y1,wy0,wy1); taps_up(x,W1,x0,x1,wx0,wx1);
        const float* ic=in+(size_t)c*V1; const int HW=H1*W1;
        float a=wz0*(wy0*(wx0*ic[z0*HW+y0*W1+x0]+wx1*ic[z0*HW+y0*W1+x1])+
                     wy1*(wx0*ic[z0*HW+y1*W1+x0]+wx1*ic[z0*HW+y1*W1+x1]))+
                wz1*(wy0*(wx0*ic[z1*HW+y0*W1+x0]+wx1*ic[z1*HW+y0*W1+x1])+
                     wy1*(wx0*ic[z1*HW+y1*W1+x0]+wx1*ic[z1*HW+y1*W1+x1]));
        out[idx]=a*scale;
    }
}

// ---------- cost volume, 4 voxels/thread, fused pair-normalization ----------
template <int MD>
__global__ void __launch_bounds__(128)
k_costvol4(const float* __restrict__ f1,const float* __restrict__ f2,
           float* __restrict__ out,int C,int D,int H,int W){
    const int N=2*MD+1;
    const int NW=2*MD+4;
    size_t V=(size_t)D*H*W; const int HW=H*W;
    const int i=blockIdx.y;
    const float invC=1.f/(float)C;
    const float m=g_ms[0], is=g_ms[1];
    const int Wq=W>>2;
    const int nquad=D*H*Wq;
    for(int q=blockIdx.x*blockDim.x+threadIdx.x;q<nquad;q+=gridDim.x*blockDim.x){
        int xb=(q%Wq)<<2; int r=q/Wq; int y=r%H; int z=r/H;
        size_t p=(size_t)z*HW+(size_t)y*W+xb;
        float acc[N*N][4];
        #pragma unroll
        for(int t=0;t<N*N;t++)
        #pragma unroll
        for(int vx=0;vx<4;vx++) acc[t][vx]=0.f;
        int zq=z+i-MD;
        if(zq>=0&&zq<D){
            for(int c=0;c<C;c++){
                float4 f1v=*(const float4*)(f1+(size_t)c*V+p);
                float tv[4]={(f1v.x-m)*is,(f1v.y-m)*is,(f1v.z-m)*is,(f1v.w-m)*is};
                const float* base=f2+(size_t)c*V+(size_t)zq*HW;
                #pragma unroll
                for(int j=0;j<N;j++){
                    int yq=y+j-MD; if(yq<0||yq>=H)continue;
                    const float* row=base+yq*W;
                    float v[NW];
                    float4 mm=*(const float4*)(row+xb);
                    v[MD+0]=(mm.x-m)*is; v[MD+1]=(mm.y-m)*is;
                    v[MD+2]=(mm.z-m)*is; v[MD+3]=(mm.w-m)*is;
                    if(MD==2){
                        if(xb>0){
                            float2 a2=*(const float2*)(row+xb-2);
                            v[0]=(a2.x-m)*is; v[1]=(a2.y-m)*is;
                        } else { v[0]=0.f; v[1]=0.f; }
                        if(xb+4<W){
                            float2 d2=*(const float2*)(row+xb+4);
                            v[6]=(d2.x-m)*is; v[7]=(d2.y-m)*is;
                        } else { v[6]=0.f; v[7]=0.f; }
                    } else {
                        v[0]=(xb>0)?(row[xb-1]-m)*is:0.f;
                        v[5]=(xb+4<W)?(row[xb+4]-m)*is:0.f;
                    }
                    #pragma unroll
                    for(int k=0;k<N;k++)
                    #pragma unroll
                    for(int vx=0;vx<4;vx++)
                        acc[j*N+k][vx]+=tv[vx]*v[vx+k];
                }
            }
        }
        #pragma unroll
        for(int j=0;j<N;j++)
        #pragma unroll
        for(int k=0;k<N;k++){
            float4 o;
            float* ap=acc[j*N+k];
            float a0=ap[0]*invC, a1=ap[1]*invC, a2=ap[2]*invC, a3=ap[3]*invC;
            o.x=(a0>=0.f)?a0:0.05f*a0;
            o.y=(a1>=0.f)?a1:0.05f*a1;
            o.z=(a2>=0.f)?a2:0.05f*a2;
            o.w=(a3>=0.f)?a3:0.05f*a3;
            *(float4*)(out+(size_t)((i*N+j)*N+k)*V+p)=o;
        }
    }
}

// ---------- unrolled per-tap MMA compute ----------
template<int KSN,int MF,int NB>
__device__ __forceinline__ void tap_compute(
    uint32_t sA_h,uint32_t sA_l,uint32_t sB_h,uint32_t sB_l,
    const uint32_t (&arow)[MF],int nbase,int bq,int bi,
    float (&acc)[MF][2*NB][4]){
    #pragma unroll
    for(int ks=0;ks<KSN;ks++){
        uint32_t ah[MF][4], al[MF][4];
        #pragma unroll
        for(int mf=0;mf<MF;mf++){
            uint32_t o=SWZ(arow[mf]+(uint32_t)ks*32);
            ldsm4(ah[mf],sA_h+o);
            ldsm4(al[mf],sA_l+o);
        }
        uint32_t bh[NB][4], bl[NB][4];
        #pragma unroll
        for(int g=0;g<NB;g++){
            int row=nbase+g*16+((bq>>1)<<3)+bi;
            uint32_t bo=SWZ((uint32_t)row*128+(uint32_t)(bq&1)*16+(uint32_t)ks*32);
            ldsm4(bh[g],sB_h+bo);
            ldsm4(bl[g],sB_l+bo);
        }
        #pragma unroll
        for(int mf=0;mf<MF;mf++)
        #pragma unroll
        for(int g=0;g<NB;g++)
        #pragma unroll
        for(int h=0;h<2;h++){
            float* C=acc[mf][g*2+h];
            mma16816(C,ah[mf],&bh[g][2*h]);
            mma16816(C,ah[mf],&bl[g][2*h]);
            mma16816(C,al[mf],&bh[g][2*h]);
        }
    }
}

// ---------- mma.sync implicit-GEMM conv (3x3x3 SAME), hi/lo bf16 ----------
// All layers: double-buffered cp.async B staging (latency hidden behind compute).
template<int NT>
__global__ void __launch_bounds__(256,2)
k_wmma_conv(const __nv_bfloat16* __restrict__ xh,const __nv_bfloat16* __restrict__ xl,
            const __nv_bfloat16* __restrict__ wh,const __nv_bfloat16* __restrict__ wl,
            const float* __restrict__ bias,
            __nv_bfloat16* oh,__nv_bfloat16* ol,float* of32,
            int Ctot,int Cin,int Cpad,int Dd,int Hh,int Ww,int coutOff){
    constexpr int MF=(NT==64)?2:1;
    constexpr int NF=(NT==64)?4:(NT/8);
    constexpr int NB=NF/2;
    constexpr uint32_t NTB=(uint32_t)NT*128;
    extern __shared__ __align__(128) char sm[];
    const uint32_t sA_h=smem_u32(sm);
    const uint32_t sA_l=sA_h+46080;
    const uint32_t sB0=sA_h+92160;

    const int tid=threadIdx.x, lane=tid&31, wid=tid>>5;
    const int x0=blockIdx.x*8, y0=blockIdx.y*4, z0=blockIdx.z*4;
    const int HW=Hh*Ww; const size_t V=(size_t)Dd*HW;
    const int mbase=(NT==64)?(wid&3)*32:wid*16;
    const int nbase=(NT==64)?(wid>>2)*32:0;

    float acc[MF][NF][4];
    #pragma unroll
    for(int a=0;a<MF;a++)
    #pragma unroll
    for(int b=0;b<NF;b++)
    #pragma unroll
    for(int c=0;c<4;c++) acc[a][b][c]=0.f;

    int lmx[MF],lmy[MF],lmz[MF];
    #pragma unroll
    for(int mf=0;mf<MF;mf++){
        int m=mbase+mf*16+(lane&15);
        lmx[mf]=m&7; lmy[mf]=(m>>3)&3; lmz[mf]=m>>5;
    }
    const uint32_t khoff=(uint32_t)(lane>>4)*16;
    const int bq=lane>>3, bi=lane&7;

    const int nchunk=(Cin+63)>>6;
    for(int ch=0;ch<nchunk;ch++){
        const int ci0=ch<<6;
        const int kreal=min(64,Cin-ci0);
        const int ksn=(kreal+15)>>4;
        const int nseg=2*ksn;
        __syncthreads();
        // ---- stage A halo ----
        for(int r=tid;r<360;r+=256){
            int hx=r%10, hy=(r/10)%6, hz=r/60;
            int gx=x0+hx-1, gy=y0+hy-1, gz=z0+hz-1;
            bool val=(gx>=0&&gx<Ww&&gy>=0&&gy<Hh&&gz>=0&&gz<Dd);
            size_t vox=val?((size_t)gz*HW+(size_t)gy*Ww+gx):0;
            const __nv_bfloat16* ph=xh+vox*(size_t)Ctot+ci0;
            const __nv_bfloat16* pl=xl+vox*(size_t)Ctot+ci0;
            uint32_t rb=(uint32_t)r*128;
            for(int s=0;s<nseg;s++){
                uint4 vh=make_uint4(0,0,0,0), vl=make_uint4(0,0,0,0);
                if(val){
                    if(s*8+8<=kreal){ vh=*(const uint4*)(ph+s*8); vl=*(const uint4*)(pl+s*8); }
                    else if(s*8<kreal){
                        uint16_t th[8]={0,0,0,0,0,0,0,0}, tl[8]={0,0,0,0,0,0,0,0};
                        for(int j=0;j<8;j++) if(s*8+j<kreal){
                            th[j]=((const uint16_t*)ph)[s*8+j];
                            tl[j]=((const uint16_t*)pl)[s*8+j];
                        }
                        vh=*(uint4*)th; vl=*(uint4*)tl;
                    }
                }
                uint32_t off=SWZ(rb+(uint32_t)s*16);
                *(uint4*)(sm+off)=vh;
                *(uint4*)(sm+46080+off)=vl;
            }
        }
        // prefetch tap 0's B into buffer 0
        for(int s=tid;s<NT*nseg;s+=256){
            int n=s/nseg, seg=s-n*nseg;
            size_t wb=((size_t)0*NT+n)*Cpad+ci0+seg*8;
            uint32_t off=SWZ((uint32_t)n*128+(uint32_t)seg*16);
            cpasync16(sB0+off,wh+wb);
            cpasync16(sB0+NTB+off,wl+wb);
        }
        CP_COMMIT();
        // ---- taps ----
        for(int tap=0;tap<27;tap++){
            __syncthreads();   // prior compute done
            if(tap<26){
                uint32_t nb_=sB0+(uint32_t)(((tap+1)&1)*2)*NTB;
                for(int s=tid;s<NT*nseg;s+=256){
                    int n=s/nseg, seg=s-n*nseg;
                    size_t wb=((size_t)(tap+1)*NT+n)*Cpad+ci0+seg*8;
                    uint32_t off=SWZ((uint32_t)n*128+(uint32_t)seg*16);
                    cpasync16(nb_+off,wh+wb);
                    cpasync16(nb_+NTB+off,wl+wb);
                }
                CP_COMMIT();
                CP_WAIT1();
            } else {
                CP_WAIT0();
            }
            uint32_t sBh=sB0+(uint32_t)((tap&1)*2)*NTB;
            uint32_t sBl=sBh+NTB;
            __syncthreads();   // B visible to all threads
            const int dz=tap/9-1, dy=(tap/3)%3-1, dx=tap%3-1;
            uint32_t arow[MF];
            #pragma unroll
            for(int mf=0;mf<MF;mf++){
                int hr=((lmz[mf]+dz+1)*6+(lmy[mf]+dy+1))*10+(lmx[mf]+dx+1);
                arow[mf]=(uint32_t)hr*128+khoff;
            }
            switch(ksn){
                case 4: tap_compute<4,MF,NB>(sA_h,sA_l,sBh,sBl,arow,nbase,bq,bi,acc); break;
                case 3: tap_compute<3,MF,NB>(sA_h,sA_l,sBh,sBl,arow,nbase,bq,bi,acc); break;
                case 2: tap_compute<2,MF,NB>(sA_h,sA_l,sBh,sBl,arow,nbase,bq,bi,acc); break;
                default: tap_compute<1,MF,NB>(sA_h,sA_l,sBh,sBl,arow,nbase,bq,bi,acc); break;
            }
        }
    }

    // ---- epilogue ----
    #pragma unroll
    for(int mf=0;mf<MF;mf++)
    #pragma unroll
    for(int nf=0;nf<NF;nf++)
    #pragma unroll
    for(int rp=0;rp<2;rp++){
        int m=mbase+mf*16+(lane>>2)+rp*8;
        int n=nbase+nf*8+((lane&3)<<1);
        int gx=x0+(m&7), gy=y0+((m>>3)&3), gz=z0+(m>>5);
        size_t vox=(size_t)gz*HW+(size_t)gy*Ww+gx;
        float v0=acc[mf][nf][rp*2+0]+bias[n];
        float v1=acc[mf][nf][rp*2+1]+bias[n+1];
        v0=(v0>=0.f)?v0:0.02f*v0;
        v1=(v1>=0.f)?v1:0.02f*v1;
        if(oh!=nullptr){
            __nv_bfloat16 h0,l0,h1,l1;
            split_hl(v0,h0,l0); split_hl(v1,h1,l1);
            uint32_t ph_=(uint32_t)__bfloat16_as_ushort(h0)|((uint32_t)__bfloat16_as_ushort(h1)<<16);
            uint32_t pl_=(uint32_t)__bfloat16_as_ushort(l0)|((uint32_t)__bfloat16_as_ushort(l1)<<16);
            *(uint32_t*)(oh+vox*(size_t)Ctot+coutOff+n)=ph_;
            *(uint32_t*)(ol+vox*(size_t)Ctot+coutOff+n)=pl_;
        }
        if(of32!=nullptr){
            of32[(size_t)n*V+vox]=v0;
            of32[(size_t)(n+1)*V+vox]=v1;
        }
    }
}

// ---------- SIMT conv 16->3, 4 voxels/thread ----------
__global__ void k_conv16_3(const float* __restrict__ in,const float* __restrict__ wg,
                           const float* __restrict__ bias,float* __restrict__ out,
                           int Dd,int Hh,int Ww){
    __shared__ float sw[1296]; __shared__ float sb[3];
    int tid=threadIdx.x;
    for(int l=tid;l<1296;l+=blockDim.x)sw[l]=wg[l];
    if(tid<3)sb[tid]=bias[tid];
    __syncthreads();
    const int HW=Hh*Ww; const size_t V=(size_t)Dd*HW;
    const int Wq=Ww>>2;
    const int nquad=Dd*Hh*Wq;
    for(int q=blockIdx.x*blockDim.x+tid;q<nquad;q+=gridDim.x*blockDim.x){
        int xq=q%Wq; int r=q/Wq; int y=r%Hh; int z=r/Hh;
        int xb=xq<<2;
        float a[3][4];
        #pragma unroll
        for(int o=0;o<3;o++)
        #pragma unroll
        for(int j=0;j<4;j++) a[o][j]=sb[o];
        for(int dz=-1;dz<=1;dz++){
            int zz=z+dz; if(zz<0||zz>=Dd)continue;
            for(int dy=-1;dy<=1;dy++){
                int yy=y+dy; if(yy<0||yy>=Hh)continue;
                int tap0=(dz+1)*9+(dy+1)*3;
                #pragma unroll 2
                for(int c=0;c<16;c++){
                    const float* row=in+(size_t)c*V+(size_t)zz*HW+(size_t)yy*Ww+xb;
                    float v[6];
                    float4 mid=*(const float4*)row;
                    v[1]=mid.x; v[2]=mid.y; v[3]=mid.z; v[4]=mid.w;
                    v[0]=(xb>0)?row[-1]:0.f;
                    v[5]=(xb+4<Ww)?row[4]:0.f;
                    #pragma unroll
                    for(int dx=0;dx<3;dx++){
                        float w0=sw[c*27+tap0+dx];
                        float w1=sw[(16+c)*27+tap0+dx];
                        float w2=sw[(32+c)*27+tap0+dx];
                        #pragma unroll
                        for(int j=0;j<4;j++){
                            float vv=v[j+dx];
                            a[0][j]+=vv*w0; a[1][j]+=vv*w1; a[2][j]+=vv*w2;
                        }
                    }
                }
            }
        }
        size_t p=(size_t)z*HW+(size_t)y*Ww+xb;
        #pragma unroll
        for(int o=0;o<3;o++)
            *(float4*)(out+(size_t)o*V+p)=make_float4(a[o][0],a[o][1],a[o][2],a[o][3]);
    }
}

// ---------- host ----------
template<int NT>
static void run_wconv(const __nv_bfloat16* xh,const __nv_bfloat16* xl,
                      const __nv_bfloat16* wh,const __nv_bfloat16* wl,const float* bias,
                      __nv_bfloat16* oh,__nv_bfloat16* ol,float* of32,
                      int Ctot,int Cin,int Cpad,int Dd,int Hh,int Ww,int coutOff){
    size_t smv=92160+4*(size_t)NT*128;
    cudaFuncSetAttribute(k_wmma_conv<NT>,cudaFuncAttributeMaxDynamicSharedMemorySize,(int)smv);
    dim3 g(Ww/8,Hh/4,Dd/4);
    k_wmma_conv<NT><<<g,256,smv>>>(xh,xl,wh,wl,bias,oh,ol,of32,Ctot,Cin,Cpad,Dd,Hh,Ww,coutOff);
}

extern "C" void kernel_launch(void* const* d_in,const int* in_sizes,int n_in,
                              void* d_out,int out_size){
    const float* t_ptr=(const float*)d_in[0];
    const float* dispup=(const float*)d_in[1];
    const float* fx=(const float*)d_in[2];
    const float* fy=(const float*)d_in[3];
    const float* fxu=(const float*)d_in[4];
    const float* fyu=(const float*)d_in[5];
    const float* ctx=(const float*)d_in[6];
    const float* w1_[5]={(const float*)d_in[7],(const float*)d_in[9],(const float*)d_in[11],
                         (const float*)d_in[13],(const float*)d_in[15]};
    const float* b1_[5]={(const float*)d_in[8],(const float*)d_in[10],(const float*)d_in[12],
                         (const float*)d_in[14],(const float*)d_in[16]};
    const float* w2_[3]={(const float*)d_in[17],(const float*)d_in[19],(const float*)d_in[21]};
    const float* b2_[3]={(const float*)d_in[18],(const float*)d_in[20],(const float*)d_in[22]};

    float* A; cudaGetSymbolAddress((void**)&A,g_arena);
    __nv_bfloat16 *xh1,*xl1,*xh2,*xl2,*wh,*wl;
    cudaGetSymbolAddress((void**)&xh1,g_xh1); cudaGetSymbolAddress((void**)&xl1,g_xl1);
    cudaGetSymbolAddress((void**)&xh2,g_xh2); cudaGetSymbolAddress((void**)&xl2,g_xl2);
    cudaGetSymbolAddress((void**)&wh,g_wh);   cudaGetSymbolAddress((void**)&wl,g_wl);

    float* xin1=A+O_XIN1;  float* xin2=A+O_XIN2;
    float* ctx16=A+O_CTX;  float* vel=A+O_VEL;   float* velup=A+O_VELUP;
    float* xout2=A+O_XOUT2;float* velup2=A+O_VELUP2;
    float* cv1=xin1;                  float* wx=xin1+157ull*V1;  float* disp=xin1+221ull*V1;
    float* cv2=xin2;                  float* wxu=xin2+43ull*V2;
    float* upctx=xin2+59ull*V2;       float* disp2=xin2+75ull*V2;
    float* outf=(float*)d_out;

    static cudaStream_t sB=nullptr;
    static cudaEvent_t evF=nullptr,evA=nullptr,evJ1=nullptr,
                       evB=nullptr,evJ2=nullptr,evC=nullptr,evJ3=nullptr;
    if(sB==nullptr){
        cudaStreamCreateWithFlags(&sB,cudaStreamNonBlocking);
        cudaEventCreateWithFlags(&evF,cudaEventDisableTiming);
        cudaEventCreateWithFlags(&evA,cudaEventDisableTiming);
        cudaEventCreateWithFlags(&evJ1,cudaEventDisableTiming);
        cudaEventCreateWithFlags(&evB,cudaEventDisableTiming);
        cudaEventCreateWithFlags(&evJ2,cudaEventDisableTiming);
        cudaEventCreateWithFlags(&evC,cudaEventDisableTiming);
        cudaEventCreateWithFlags(&evJ3,cudaEventDisableTiming);
    }

    const int TPB=256, GB1=(V1+TPB-1)/TPB, GB2=(V2+TPB-1)/TPB;
    cudaMemsetAsync(d_out,0,(size_t)out_size*sizeof(float),0);

    // ---- fork 0: weight prep + true-input packs ----
    cudaEventRecord(evF,0);
    cudaStreamWaitEvent(sB,evF,0);
    k_prep_w<<<512,256,0,sB>>>(w1_[0],wh+WOFF0,wl+WOFF0,64,64,224,256);
    k_prep_w<<<512,256,0,sB>>>(w1_[1],wh+WOFF1,wl+WOFF1,48,48,288,320);
    k_prep_w<<<512,256,0,sB>>>(w1_[2],wh+WOFF2,wl+WOFF2,32,32,336,384);
    k_prep_w<<<512,256,0,sB>>>(w1_[3],wh+WOFF3,wl+WOFF3,16,16,368,384);
    k_prep_w<<<256,256,0,sB>>>(w2_[0],wh+WOFF4,wl+WOFF4,32,32,78,128);
    k_prep_w<<<256,256,0,sB>>>(w2_[1],wh+WOFF5,wl+WOFF5,16,16,110,128);
    k_pack_hl_t<<<V1/64,256,0,sB>>>(fy,  xh1,xl1,V1,368,125,32);
    k_pack_hl_t<<<V1/64,256,0,sB>>>(ctx, xh1,xl1,V1,368,189,32);
    k_pack_hl_t<<<V2/64,256,0,sB>>>(fyu, xh2,xl2,V2,112,27,16);

    // ---- coarse chain ----
    k_resize_down<<<(3*V1+TPB-1)/TPB,TPB>>>(dispup,disp,0.5f);
    k_warp<<<GB1,TPB>>>(fx,disp,wx,32,D1,H1,W1,0);
    cudaEventRecord(evA,0);
    cudaStreamWaitEvent(sB,evA,0);
    k_pack_hl_t<<<V1/64,256,0,sB>>>(wx,  xh1,xl1,V1,368,157,32);
    k_pack_hl_t<<<V1/64,256,0,sB>>>(disp,xh1,xl1,V1,368,221,3);
    cudaEventRecord(evJ1,sB);

    k_zero_red<<<1,4>>>();
    k_reduce4<<<1024,256>>>((const float4*)wx,8*V1,0);
    k_reduce4<<<1024,256>>>((const float4*)fy,8*V1,2);
    k_finalize_ms<<<1,1>>>((double)(32*V1));
    {
        int nq=D1*H1*(W1/4);
        k_costvol4<2><<<dim3((nq+127)/128,5),128>>>(fy,wx,cv1,32,D1,H1,W1);
    }
    k_pack_hl_t<<<V1/64,256>>>(cv1, xh1,xl1,V1,368,0,  125);

    cudaStreamWaitEvent(0,evJ1,0);

    // fl1 dense block
    run_wconv<64>(xh1,xl1,wh+WOFF0,wl+WOFF0,b1_[0],xh1,xl1,nullptr,368,224,256,D1,H1,W1,224);
    run_wconv<48>(xh1,xl1,wh+WOFF1,wl+WOFF1,b1_[1],xh1,xl1,nullptr,368,288,320,D1,H1,W1,288);
    run_wconv<32>(xh1,xl1,wh+WOFF2,wl+WOFF2,b1_[2],xh1,xl1,nullptr,368,336,384,D1,H1,W1,336);
    run_wconv<16>(xh1,xl1,wh+WOFF3,wl+WOFF3,b1_[3],nullptr,nullptr,ctx16,368,368,384,D1,H1,W1,0);
    cudaEventRecord(evB,0);
    cudaStreamWaitEvent(sB,evB,0);
    k_resize_up<<<GB2*2,256,0,sB>>>(ctx16,upctx,16,1.0f);
    k_pack_hl_t<<<V2/64,256,0,sB>>>(upctx,xh2,xl2,V2,112,59,16);
    cudaEventRecord(evJ2,sB);

    k_conv16_3<<<(V1/4+TPB-1)/TPB,TPB>>>(ctx16,w1_[4],b1_[4],vel,D1,H1,W1);

    // ---- fine chain ----
    k_resize_up<<<GB2,TPB>>>(vel,velup,3,2.0f);
    k_warp<<<GB2,TPB>>>(dispup,velup,disp2,3,D2,H2,W2,1);
    k_warp<<<GB2,TPB>>>(fxu,disp2,wxu,16,D2,H2,W2,0);
    cudaEventRecord(evC,0);
    cudaStreamWaitEvent(sB,evC,0);
    k_pack_hl_t<<<V2/64,256,0,sB>>>(wxu,  xh2,xl2,V2,112,43,16);
    k_pack_hl_t<<<V2/64,256,0,sB>>>(disp2,xh2,xl2,V2,112,75,3);
    cudaEventRecord(evJ3,sB);

    k_zero_red<<<1,4>>>();
    k_reduce4<<<1024,256>>>((const float4*)wxu,4*V2,0);
    k_reduce4<<<1024,256>>>((const float4*)fyu,4*V2,2);
    k_finalize_ms<<<1,1>>>((double)(16*V2));
    {
        int nq=D2*H2*(W2/4);
        k_costvol4<1><<<dim3((nq+127)/128,3),128>>>(fyu,wxu,cv2,16,D2,H2,W2);
    }
    k_pack_hl_t<<<V2/64,256>>>(cv2,  xh2,xl2,V2,112,0, 27);

    cudaStreamWaitEvent(0,evJ2,0);
    cudaStreamWaitEvent(0,evJ3,0);

    // fl2 dense block
    run_wconv<32>(xh2,xl2,wh+WOFF4,wl+WOFF4,b2_[0],xh2,xl2,nullptr,112,78,128,D2,H2,W2,78);
    run_wconv<16>(xh2,xl2,wh+WOFF5,wl+WOFF5,b2_[1],nullptr,nullptr,xout2,112,110,128,D2,H2,W2,0);
    k_conv16_3<<<(V2/4+TPB-1)/TPB,TPB>>>(xout2,w2_[2],b2_[2],velup2,D2,H2,W2);

    {
        int nq=D2*H2*(W2/4);
        k_final<<<(nq+TPB-1)/TPB,TPB>>>(disp2,velup2,dispup,t_ptr,outf);
    }
}